// round 12
// baseline (speedup 1.0000x reference)
#include <cuda_runtime.h>
#include <cuda_fp16.h>
#include <cstdint>
#include <math.h>

// Problem constants
#define B_ 4
#define T_ 2048
#define C_ 1024
#define H_ 16
#define D_ 64
#define BH_ (B_ * H_)

// Scratch (device globals -- no allocation allowed)
__device__ __half g_q16[BH_ * T_ * D_];     // [B,H,T,D]
__device__ __half g_k16[BH_ * T_ * D_];     // [B,H,T,D]
__device__ __half g_vt16[BH_ * D_ * T_];    // [B,H,D,T]  (V transposed)
__device__ __half g_y16[B_ * T_ * C_];      // [B,T,C]
__device__ __half g_x16[B_ * T_ * C_];      // x -> half
__device__ __half g_wqkvT16[3 * C_ * C_];   // [3C, C] = W_qkv^T
__device__ __half g_woutT16[C_ * C_];       // [C, C]  = W_out^T

// Flag counters for the in-kernel pipeline (zeroed by prep each call)
__device__ int g_cnt0[64];   // per qkv row-tile: col-tiles done (24 = ready)
__device__ int g_cnt1[64];   // per (b,qi) group: heads done (16 = ready)

// ---------------------------------------------------------------------------
// Helpers
// ---------------------------------------------------------------------------
__device__ __forceinline__ uint32_t smem_u32(const void* p) {
    return (uint32_t)__cvta_generic_to_shared(p);
}

__device__ __forceinline__ float ex2f(float x) {
    float y;
    asm("ex2.approx.f32 %0, %1;" : "=f"(y) : "f"(x));
    return y;
}

__device__ __forceinline__ uint32_t packh2(float a, float b) {
    __half2 h = __floats2half2_rn(a, b);
    return *(uint32_t*)&h;
}

__device__ __forceinline__ void mma_f16(float d[4], const uint32_t a[4],
                                        const uint32_t b[2], const float c[4]) {
    asm volatile(
        "mma.sync.aligned.m16n8k16.row.col.f32.f16.f16.f32 "
        "{%0,%1,%2,%3},{%4,%5,%6,%7},{%8,%9},{%10,%11,%12,%13};"
        : "=f"(d[0]), "=f"(d[1]), "=f"(d[2]), "=f"(d[3])
        : "r"(a[0]), "r"(a[1]), "r"(a[2]), "r"(a[3]),
          "r"(b[0]), "r"(b[1]),
          "f"(c[0]), "f"(c[1]), "f"(c[2]), "f"(c[3]));
}

__device__ __forceinline__ void ldsm_x4(uint32_t d[4], uint32_t saddr) {
    asm volatile(
        "ldmatrix.sync.aligned.m8n8.x4.shared.b16 {%0,%1,%2,%3}, [%4];"
        : "=r"(d[0]), "=r"(d[1]), "=r"(d[2]), "=r"(d[3]) : "r"(saddr));
}

__device__ __forceinline__ void cp_async16(uint32_t dst, const void* src) {
    asm volatile("cp.async.cg.shared.global [%0], [%1], 16;"
                 :: "r"(dst), "l"(src) : "memory");
}
__device__ __forceinline__ void cp_commit() {
    asm volatile("cp.async.commit_group;" ::: "memory");
}
template <int N>
__device__ __forceinline__ void cp_wait() {
    asm volatile("cp.async.wait_group %0;" :: "n"(N) : "memory");
}

// ---------------------------------------------------------------------------
// Unified prep kernel (one launch):
//   bids [0,8192):      x -> half (2M float4)
//   bids [8192,11264):  transpose Wqkv [1024,3072] -> [3072,1024] half
//   bids [11264,12288): transpose Wout [1024,1024] -> [1024,1024] half
//   bid 0 also zeroes the pipeline flags.
// ---------------------------------------------------------------------------
#define PREP_GRID 12288

__global__ __launch_bounds__(256) void prep_kernel(
    const float* __restrict__ x,
    const float* __restrict__ Wqkv,
    const float* __restrict__ Wout)
{
    __shared__ float t[32][33];
    const int bid = blockIdx.x;
    const int tid = threadIdx.x;

    if (bid == 0 && tid < 64) {
        g_cnt0[tid] = 0;
        g_cnt1[tid] = 0;
    }

    if (bid < 8192) {
        int i = bid * 256 + tid;
        float4 v = ((const float4*)x)[i];
        __half2* o = (__half2*)(g_x16 + (size_t)i * 4);
        o[0] = __floats2half2_rn(v.x, v.y);
        o[1] = __floats2half2_rn(v.z, v.w);
        return;
    }

    // transpose: in [R=1024, Ccols], out [Ccols, 1024] half
    const float* in;
    __half* outp;
    int Ccols, bx, by;
    if (bid < 11264) {
        int id = bid - 8192;           // 96 x 32 tiles
        in = Wqkv; outp = g_wqkvT16; Ccols = 3072;
        bx = (id % 96) * 32; by = (id / 96) * 32;
    } else {
        int id = bid - 11264;          // 32 x 32 tiles
        in = Wout; outp = g_woutT16; Ccols = 1024;
        bx = (id % 32) * 32; by = (id / 32) * 32;
    }
    const int xL = tid & 31;
    const int yL = tid >> 5;           // 0..7
#pragma unroll
    for (int j = 0; j < 32; j += 8)
        t[yL + j][xL] = in[(size_t)(by + yL + j) * Ccols + bx + xL];
    __syncthreads();
#pragma unroll
    for (int j = 0; j < 32; j += 8)
        outp[(size_t)(bx + yL + j) * 1024 + by + xL] = __float2half_rn(t[xL][yL + j]);
}

// ---------------------------------------------------------------------------
// FP16 GEMM body: C[m0..][N] tile = A @ Bt^T + bias (fp32 acc)
// BM=128 BN=128 BK=64 halves, 256 threads (8 warps 2x4), warp tile 64x32.
// cp.async 3-stage, 1 sync/iter, ldmatrix both operands.
// MODE 0: convert to half + scatter q/k (BHTD) and vt (BHDT).
// MODE 1: fp32 row-major store + bias.
// ---------------------------------------------------------------------------
#define GKT 16                    // k-tiles (K=1024 / 64)
#define STAGE_B 16384             // 128 rows x 128B
#define GEMM_SMEM (6 * STAGE_B)   // 3 stages x (A+B) = 98304

template <int MODE>
__device__ __forceinline__ void gemm_body(
    char* smem, const __half* __restrict__ Ag, const __half* __restrict__ Bg,
    const float* __restrict__ bias, float* __restrict__ Cout, int N,
    int m0, int n0)
{
    const uint32_t sA = smem_u32(smem);
    const uint32_t sB = sA + 3 * STAGE_B;

    const int tid  = threadIdx.x;
    const int lane = tid & 31;
    const int wid  = tid >> 5;
    const int wr   = (wid >> 2) * 64;
    const int wc   = (wid & 3) * 32;

    const int lr = tid >> 3;      // + i*32
    const int lg = tid & 7;       // 16B group (8 halves)

    auto issue = [&](int kt) {
        const int s = kt % 3;
#pragma unroll
        for (int i = 0; i < 4; i++) {
            int r = lr + i * 32;
            uint32_t off = r * 128 + ((lg ^ (r & 7)) << 4);
            cp_async16(sA + s * STAGE_B + off,
                       Ag + (size_t)(m0 + r) * 1024 + kt * 64 + lg * 8);
            cp_async16(sB + s * STAGE_B + off,
                       Bg + (size_t)(n0 + r) * 1024 + kt * 64 + lg * 8);
        }
        cp_commit();
    };

    const int arow  = wr + (lane & 7) + 8 * ((lane >> 3) & 1);
    const int kha   = lane >> 4;
    const int brow0 = wc + (lane & 7) + 8 * (lane >> 4);
    const int khb   = (lane >> 3) & 1;

    float acc[4][4][4];
#pragma unroll
    for (int mi = 0; mi < 4; mi++)
#pragma unroll
        for (int ni = 0; ni < 4; ni++)
#pragma unroll
            for (int r = 0; r < 4; r++) acc[mi][ni][r] = 0.0f;

    issue(0);
    issue(1);

    for (int kt = 0; kt < GKT; kt++) {
        if (kt + 1 < GKT) cp_wait<1>(); else cp_wait<0>();
        __syncthreads();
        if (kt + 2 < GKT) issue(kt + 2);

        const int s = kt % 3;
        const uint32_t aS = sA + s * STAGE_B;
        const uint32_t bS = sB + s * STAGE_B;

#pragma unroll
        for (int kk = 0; kk < 4; kk++) {
            uint32_t af[4][4];
#pragma unroll
            for (int mi = 0; mi < 4; mi++) {
                int r = arow + mi * 16;
                uint32_t addr = aS + r * 128 +
                                ((((kk << 1) | kha) ^ (r & 7)) << 4);
                ldsm_x4(af[mi], addr);
            }
            uint32_t bf[4][2];
#pragma unroll
            for (int p = 0; p < 2; p++) {
                int r = brow0 + p * 16;
                uint32_t addr = bS + r * 128 +
                                ((((kk << 1) | khb) ^ (r & 7)) << 4);
                uint32_t d[4];
                ldsm_x4(d, addr);
                bf[2 * p][0] = d[0]; bf[2 * p][1] = d[1];
                bf[2 * p + 1][0] = d[2]; bf[2 * p + 1][1] = d[3];
            }
#pragma unroll
            for (int mi = 0; mi < 4; mi++)
#pragma unroll
                for (int ni = 0; ni < 4; ni++)
                    mma_f16(acc[mi][ni], af[mi], bf[ni], acc[mi][ni]);
        }
    }

    // Epilogue
    const int g  = lane >> 2;
    const int tg = lane & 3;
#pragma unroll
    for (int mi = 0; mi < 4; mi++) {
#pragma unroll
        for (int ni = 0; ni < 4; ni++) {
#pragma unroll
            for (int r = 0; r < 4; r++) {
                int row = m0 + wr + mi * 16 + g + ((r >> 1) ? 8 : 0);
                int col = n0 + wc + ni * 8 + tg * 2 + (r & 1);
                float v = acc[mi][ni][r] + __ldg(&bias[col]);
                if (MODE == 0) {
                    __half hv = __float2half_rn(v);
                    int b = row >> 11;
                    int t = row & (T_ - 1);
                    int which = col >> 10;
                    int rr = col & (C_ - 1);
                    int h = rr >> 6;
                    int d = rr & 63;
                    size_t bhh = (size_t)(b * H_ + h);
                    if (which == 2) {
                        g_vt16[(bhh * D_ + d) * T_ + t] = hv;
                    } else {
                        __half* dst = (which == 0) ? g_q16 : g_k16;
                        dst[(bhh * T_ + t) * D_ + d] = hv;
                    }
                } else {
                    Cout[(size_t)row * N + col] = v;
                }
            }
        }
    }
}

// ---------------------------------------------------------------------------
// Flash attention body (causal), fp16 mma, BQ=128 BKV=64, 256 threads
// (8 warps, one 16-row q slab each). FA2: P in registers. K/Vt 3-stage
// cp.async ring, 1 sync/iter. Softmax fp32 base-2.
// ---------------------------------------------------------------------------
#define AQB 16384                        // Q: 128 rows x 128B
#define AKV 8192                         // K/Vt tile: 64 rows x 128B
#define AQ_OFF 0
#define AK_OFF AQB                       // + s*AKV   (3 stages)
#define AV_OFF (AQB + 3 * AKV)           // + s*AKV   (3 stages)

__device__ __forceinline__ void attn_body(char* smc, int b, int h, int qi)
{
    const uint32_t sQ = smem_u32(smc);
    const int bh  = b * H_ + h;
    const int tid = threadIdx.x;
    const int lane = tid & 31;
    const int wid  = tid >> 5;
    const int g    = lane >> 2;
    const int tg   = lane & 3;

    const __half* Qg  = g_q16  + ((size_t)bh * T_ + qi * 128) * D_;
    const __half* Kg  = g_k16  + (size_t)bh * T_ * D_;
    const __half* Vtg = g_vt16 + (size_t)bh * D_ * T_;

    // Q tile (128x64 halves) -> swizzled smem
#pragma unroll
    for (int it = 0; it < 4; it++) {
        int i = tid + it * 256;
        int r = i >> 3, gg = i & 7;
        uint4 v = *(const uint4*)&Qg[r * 64 + gg * 8];
        *(uint4*)(smc + r * 128 + ((gg ^ (r & 7)) << 4)) = v;
    }

    auto issue = [&](int j) {
        const int s = j % 3;
#pragma unroll
        for (int it = 0; it < 2; it++) {
            int i = tid + it * 256;
            int r = i >> 3, gg = i & 7;
            uint32_t sw = r * 128 + ((gg ^ (r & 7)) << 4);
            cp_async16(sQ + AK_OFF + s * AKV + sw,
                       Kg + ((size_t)j * 64 + r) * 64 + gg * 8);
            cp_async16(sQ + AV_OFF + s * AKV + sw,
                       Vtg + (size_t)r * T_ + j * 64 + gg * 8);
        }
        cp_commit();
    };

    const int jmax = 2 * qi + 1;
    issue(0);
    issue(1);

    // fragment lane constants
    const int qrow = wid * 16 + (lane & 7) + 8 * ((lane >> 3) & 1);
    const int khq  = lane >> 4;
    const int qxk  = qrow & 7;
    const uint32_t qbase = sQ + AQ_OFF + qrow * 128;
    const int brow = (lane & 7) + 8 * (lane >> 4);    // + p*16
    const int khb  = (lane >> 3) & 1;

    float O[8][4];
#pragma unroll
    for (int ni = 0; ni < 8; ni++)
#pragma unroll
        for (int r = 0; r < 4; r++) O[ni][r] = 0.0f;
    float mrow0 = -1e30f, mrow1 = -1e30f;
    float lrow0 = 0.0f,   lrow1 = 0.0f;

    const int rloc = wid * 16 + g;
    const float scale = 0.125f * 1.4426950408889634f;   // 1/sqrt(D) * log2(e)

    for (int j = 0; j <= jmax; j++) {
        const int s = j % 3;
        if (j < jmax) cp_wait<1>(); else cp_wait<0>();
        __syncthreads();
        if (j + 2 <= jmax) issue(j + 2);

        const uint32_t kS = sQ + AK_OFF + s * AKV;
        const uint32_t vS = sQ + AV_OFF + s * AKV;

        // S = Q K^T  (fp32 accum)
        float sfr[8][4];
#pragma unroll
        for (int ni = 0; ni < 8; ni++)
#pragma unroll
            for (int r = 0; r < 4; r++) sfr[ni][r] = 0.0f;

#pragma unroll
        for (int kk = 0; kk < 4; kk++) {
            uint32_t af[4];
            ldsm_x4(af, qbase + ((((kk << 1) | khq) ^ qxk) << 4));
            uint32_t bf[8][2];
#pragma unroll
            for (int p = 0; p < 4; p++) {
                int r = brow + p * 16;
                uint32_t d[4];
                ldsm_x4(d, kS + r * 128 + ((((kk << 1) | khb) ^ (r & 7)) << 4));
                bf[2 * p][0] = d[0]; bf[2 * p][1] = d[1];
                bf[2 * p + 1][0] = d[2]; bf[2 * p + 1][1] = d[3];
            }
#pragma unroll
            for (int ni = 0; ni < 8; ni++)
                mma_f16(sfr[ni], af, bf[ni], sfr[ni]);
        }

        // Scale (base-2) + causal mask (last two kv tiles straddle diagonal)
        const bool diag = (j >= 2 * qi);
        const int rowg0 = qi * 128 + rloc;
        const int rowg1 = rowg0 + 8;
#pragma unroll
        for (int ni = 0; ni < 8; ni++) {
#pragma unroll
            for (int r = 0; r < 4; r++) {
                float sv = sfr[ni][r] * scale;
                if (diag) {
                    int colg = j * 64 + ni * 8 + tg * 2 + (r & 1);
                    int rowg = (r >> 1) ? rowg1 : rowg0;
                    if (colg > rowg) sv = -1e30f;
                }
                sfr[ni][r] = sv;
            }
        }

        // Online softmax (base-2; two rows per thread)
        float mx0 = -1e30f, mx1 = -1e30f;
#pragma unroll
        for (int ni = 0; ni < 8; ni++) {
            mx0 = fmaxf(mx0, fmaxf(sfr[ni][0], sfr[ni][1]));
            mx1 = fmaxf(mx1, fmaxf(sfr[ni][2], sfr[ni][3]));
        }
        mx0 = fmaxf(mx0, __shfl_xor_sync(0xffffffffu, mx0, 1));
        mx0 = fmaxf(mx0, __shfl_xor_sync(0xffffffffu, mx0, 2));
        mx1 = fmaxf(mx1, __shfl_xor_sync(0xffffffffu, mx1, 1));
        mx1 = fmaxf(mx1, __shfl_xor_sync(0xffffffffu, mx1, 2));

        float mn0 = fmaxf(mrow0, mx0);
        float mn1 = fmaxf(mrow1, mx1);
        float a0 = ex2f(mrow0 - mn0);
        float a1 = ex2f(mrow1 - mn1);

        float rs0 = 0.0f, rs1 = 0.0f;
#pragma unroll
        for (int ni = 0; ni < 8; ni++) {
            float p0 = ex2f(sfr[ni][0] - mn0); sfr[ni][0] = p0; rs0 += p0;
            float p1 = ex2f(sfr[ni][1] - mn0); sfr[ni][1] = p1; rs0 += p1;
            float p2 = ex2f(sfr[ni][2] - mn1); sfr[ni][2] = p2; rs1 += p2;
            float p3 = ex2f(sfr[ni][3] - mn1); sfr[ni][3] = p3; rs1 += p3;
        }
        rs0 += __shfl_xor_sync(0xffffffffu, rs0, 1);
        rs0 += __shfl_xor_sync(0xffffffffu, rs0, 2);
        rs1 += __shfl_xor_sync(0xffffffffu, rs1, 1);
        rs1 += __shfl_xor_sync(0xffffffffu, rs1, 2);

        lrow0 = lrow0 * a0 + rs0;
        lrow1 = lrow1 * a1 + rs1;
        mrow0 = mn0;
        mrow1 = mn1;

#pragma unroll
        for (int ni = 0; ni < 8; ni++) {
            O[ni][0] *= a0; O[ni][1] *= a0;
            O[ni][2] *= a1; O[ni][3] *= a1;
        }

        // O += P @ V : FA2 repack — S accumulator fragment IS the PV
        // A-operand fragment.
#pragma unroll
        for (int kk = 0; kk < 4; kk++) {
            uint32_t af[4];
            af[0] = packh2(sfr[2 * kk    ][0], sfr[2 * kk    ][1]);
            af[1] = packh2(sfr[2 * kk    ][2], sfr[2 * kk    ][3]);
            af[2] = packh2(sfr[2 * kk + 1][0], sfr[2 * kk + 1][1]);
            af[3] = packh2(sfr[2 * kk + 1][2], sfr[2 * kk + 1][3]);
            uint32_t bf[8][2];
#pragma unroll
            for (int p = 0; p < 4; p++) {
                int r = brow + p * 16;
                uint32_t d[4];
                ldsm_x4(d, vS + r * 128 + ((((kk << 1) | khb) ^ (r & 7)) << 4));
                bf[2 * p][0] = d[0]; bf[2 * p][1] = d[1];
                bf[2 * p + 1][0] = d[2]; bf[2 * p + 1][1] = d[3];
            }
#pragma unroll
            for (int ni = 0; ni < 8; ni++)
                mma_f16(O[ni], af, bf[ni], O[ni]);
        }
    }

    // Epilogue: O /= l, convert to half, write [B,T,H,D]
    float il0 = 1.0f / lrow0;
    float il1 = 1.0f / lrow1;
    int t0 = qi * 128 + rloc;
#pragma unroll
    for (int ni = 0; ni < 8; ni++) {
        int d = ni * 8 + tg * 2;
        size_t base0 = ((size_t)(b * T_ + t0    ) * H_ + h) * D_ + d;
        size_t base1 = ((size_t)(b * T_ + t0 + 8) * H_ + h) * D_ + d;
        *(__half2*)&g_y16[base0] = __floats2half2_rn(O[ni][0] * il0, O[ni][1] * il0);
        *(__half2*)&g_y16[base1] = __floats2half2_rn(O[ni][2] * il1, O[ni][3] * il1);
    }
}

// ---------------------------------------------------------------------------
// Mega kernel: per-batch interleaved pipeline (bid order IS the schedule).
// Batch block of 768 bids: [gemm 384 | attn 256 | outproj 128].
// Consumers wait only on strictly-lower-bid producers -> deadlock-free.
// ---------------------------------------------------------------------------
#define MEGA_GRID 3072

__global__ __launch_bounds__(256, 2) void mega_kernel(
    const float* __restrict__ bqkv, const float* __restrict__ bout,
    float* __restrict__ out)
{
    extern __shared__ char smc[];
    const int bid = blockIdx.x;
    const int b   = bid / 768;
    const int rem = bid - b * 768;

    if (rem < 384) {
        // ---- QKV GEMM tile (qi_r ascending within batch) ----
        int qi_r = rem / 24;
        int ct = rem % 24;
        int rt = b * 16 + qi_r;
        gemm_body<0>(smc, g_x16, g_wqkvT16, bqkv, nullptr, 3 * C_,
                     rt * 128, ct * 128);
        __syncthreads();
        if (threadIdx.x == 0) {
            __threadfence();
            atomicAdd(&g_cnt0[rt], 1);
        }
    } else if (rem < 640) {
        // ---- attention (qi ascending within batch) ----
        int idx = rem - 384;
        int qi = idx >> 4;
        int h = idx & 15;
        if (threadIdx.x == 0) {
            for (int i = 0; i <= qi; i++)
                while (atomicAdd(&g_cnt0[b * 16 + i], 0) < 24) __nanosleep(128);
        }
        __syncthreads();
        attn_body(smc, b, h, qi);
        __syncthreads();
        if (threadIdx.x == 0) {
            __threadfence();
            atomicAdd(&g_cnt1[b * 16 + qi], 1);
        }
    } else {
        // ---- out-projection tile ----
        int idx = rem - 640;
        int qi_g = idx >> 3;
        int c = idx & 7;
        int grp = b * 16 + qi_g;
        if (threadIdx.x == 0) {
            while (atomicAdd(&g_cnt1[grp], 0) < 16) __nanosleep(128);
        }
        __syncthreads();
        gemm_body<1>(smc, g_y16, g_woutT16, bout, out, C_,
                     grp * 128, c * 128);
    }
}

// ---------------------------------------------------------------------------
// Launch
// ---------------------------------------------------------------------------
extern "C" void kernel_launch(void* const* d_in, const int* in_sizes, int n_in,
                              void* d_out, int out_size)
{
    const float* x     = (const float*)d_in[0];
    const float* Wqkv  = (const float*)d_in[1];
    const float* bqkv  = (const float*)d_in[2];
    const float* Wout  = (const float*)d_in[3];
    const float* bout  = (const float*)d_in[4];
    float* out = (float*)d_out;

    cudaFuncSetAttribute(mega_kernel,
                         cudaFuncAttributeMaxDynamicSharedMemorySize, GEMM_SMEM);

    // 0) prep: x -> half, W^T -> half, zero flags (one launch)
    prep_kernel<<<PREP_GRID, 256>>>(x, Wqkv, Wout);

    // 1) fused qkv-gemm -> attention -> out-proj pipeline, one launch
    mega_kernel<<<MEGA_GRID, 256, GEMM_SMEM>>>(bqkv, bout, out);
}

// round 13
// speedup vs baseline: 1.2713x; 1.2713x over previous
#include <cuda_runtime.h>
#include <cuda_fp16.h>
#include <cstdint>
#include <math.h>

// Problem constants
#define B_ 4
#define T_ 2048
#define C_ 1024
#define H_ 16
#define D_ 64
#define BH_ (B_ * H_)

// Scratch (device globals -- no allocation allowed)
__device__ __half g_q16[BH_ * T_ * D_];     // [B,H,T,D]
__device__ __half g_k16[BH_ * T_ * D_];     // [B,H,T,D]
__device__ __half g_vt16[BH_ * D_ * T_];    // [B,H,D,T]  (V transposed)
__device__ __half g_y16[B_ * T_ * C_];      // [B,T,C]
__device__ __half g_x16[B_ * T_ * C_];      // x -> half
__device__ __half g_wqkvT16[3 * C_ * C_];   // [3C, C] = W_qkv^T
__device__ __half g_woutT16[C_ * C_];       // [C, C]  = W_out^T

// Flag counters for the in-kernel pipeline (zeroed by prep each call)
__device__ int g_cnt0[64];   // per qkv row-tile: col-tiles done (24 = ready)
__device__ int g_cnt1[64];   // per (b,qi) group: heads done (16 = ready)

// ---------------------------------------------------------------------------
// Helpers
// ---------------------------------------------------------------------------
__device__ __forceinline__ uint32_t smem_u32(const void* p) {
    return (uint32_t)__cvta_generic_to_shared(p);
}

__device__ __forceinline__ float ex2f(float x) {
    float y;
    asm("ex2.approx.f32 %0, %1;" : "=f"(y) : "f"(x));
    return y;
}

__device__ __forceinline__ uint32_t packh2(float a, float b) {
    __half2 h = __floats2half2_rn(a, b);
    return *(uint32_t*)&h;
}

__device__ __forceinline__ void mma_f16(float d[4], const uint32_t a[4],
                                        const uint32_t b[2], const float c[4]) {
    asm volatile(
        "mma.sync.aligned.m16n8k16.row.col.f32.f16.f16.f32 "
        "{%0,%1,%2,%3},{%4,%5,%6,%7},{%8,%9},{%10,%11,%12,%13};"
        : "=f"(d[0]), "=f"(d[1]), "=f"(d[2]), "=f"(d[3])
        : "r"(a[0]), "r"(a[1]), "r"(a[2]), "r"(a[3]),
          "r"(b[0]), "r"(b[1]),
          "f"(c[0]), "f"(c[1]), "f"(c[2]), "f"(c[3]));
}

__device__ __forceinline__ void ldsm_x4(uint32_t d[4], uint32_t saddr) {
    asm volatile(
        "ldmatrix.sync.aligned.m8n8.x4.shared.b16 {%0,%1,%2,%3}, [%4];"
        : "=r"(d[0]), "=r"(d[1]), "=r"(d[2]), "=r"(d[3]) : "r"(saddr));
}

__device__ __forceinline__ void cp_async16(uint32_t dst, const void* src) {
    asm volatile("cp.async.cg.shared.global [%0], [%1], 16;"
                 :: "r"(dst), "l"(src) : "memory");
}
__device__ __forceinline__ void cp_commit() {
    asm volatile("cp.async.commit_group;" ::: "memory");
}
template <int N>
__device__ __forceinline__ void cp_wait() {
    asm volatile("cp.async.wait_group %0;" :: "n"(N) : "memory");
}

// ---------------------------------------------------------------------------
// Unified prep kernel (one launch):
//   bids [0,8192):      x -> half (2M float4)
//   bids [8192,11264):  transpose Wqkv [1024,3072] -> [3072,1024] half
//   bids [11264,12288): transpose Wout [1024,1024] -> [1024,1024] half
//   bid 0 also zeroes the pipeline flags.
// ---------------------------------------------------------------------------
#define PREP_GRID 12288

__global__ __launch_bounds__(256) void prep_kernel(
    const float* __restrict__ x,
    const float* __restrict__ Wqkv,
    const float* __restrict__ Wout)
{
    __shared__ float t[32][33];
    const int bid = blockIdx.x;
    const int tid = threadIdx.x;

    if (bid == 0 && tid < 64) {
        g_cnt0[tid] = 0;
        g_cnt1[tid] = 0;
    }

    if (bid < 8192) {
        int i = bid * 256 + tid;
        float4 v = ((const float4*)x)[i];
        __half2* o = (__half2*)(g_x16 + (size_t)i * 4);
        o[0] = __floats2half2_rn(v.x, v.y);
        o[1] = __floats2half2_rn(v.z, v.w);
        return;
    }

    // transpose: in [R=1024, Ccols], out [Ccols, 1024] half
    const float* in;
    __half* outp;
    int Ccols, bx, by;
    if (bid < 11264) {
        int id = bid - 8192;           // 96 x 32 tiles
        in = Wqkv; outp = g_wqkvT16; Ccols = 3072;
        bx = (id % 96) * 32; by = (id / 96) * 32;
    } else {
        int id = bid - 11264;          // 32 x 32 tiles
        in = Wout; outp = g_woutT16; Ccols = 1024;
        bx = (id % 32) * 32; by = (id / 32) * 32;
    }
    const int xL = tid & 31;
    const int yL = tid >> 5;           // 0..7
#pragma unroll
    for (int j = 0; j < 32; j += 8)
        t[yL + j][xL] = in[(size_t)(by + yL + j) * Ccols + bx + xL];
    __syncthreads();
#pragma unroll
    for (int j = 0; j < 32; j += 8)
        outp[(size_t)(bx + yL + j) * 1024 + by + xL] = __float2half_rn(t[xL][yL + j]);
}

// ---------------------------------------------------------------------------
// FP16 GEMM body: C[m0..][N] tile = A @ Bt^T + bias (fp32 acc)
// BM=128 BN=128 BK=64 halves, 256 threads (8 warps 2x4), warp tile 64x32.
// cp.async 3-stage, 1 sync/iter, ldmatrix both operands.
// MODE 0: convert to half + scatter q/k (BHTD, half2) and vt (BHDT, scalar).
// MODE 1: fp32 row-major store (float2) + bias.
// ---------------------------------------------------------------------------
#define GKT 16                    // k-tiles (K=1024 / 64)
#define STAGE_B 16384             // 128 rows x 128B
#define GEMM_SMEM (6 * STAGE_B)   // 3 stages x (A+B) = 98304

template <int MODE>
__device__ __forceinline__ void gemm_body(
    char* smem, const __half* __restrict__ Ag, const __half* __restrict__ Bg,
    const float* __restrict__ bias, float* __restrict__ Cout, int N,
    int m0, int n0)
{
    const uint32_t sA = smem_u32(smem);
    const uint32_t sB = sA + 3 * STAGE_B;

    const int tid  = threadIdx.x;
    const int lane = tid & 31;
    const int wid  = tid >> 5;
    const int wr   = (wid >> 2) * 64;
    const int wc   = (wid & 3) * 32;

    const int lr = tid >> 3;      // + i*32
    const int lg = tid & 7;       // 16B group (8 halves)

    auto issue = [&](int kt) {
        const int s = kt % 3;
#pragma unroll
        for (int i = 0; i < 4; i++) {
            int r = lr + i * 32;
            uint32_t off = r * 128 + ((lg ^ (r & 7)) << 4);
            cp_async16(sA + s * STAGE_B + off,
                       Ag + (size_t)(m0 + r) * 1024 + kt * 64 + lg * 8);
            cp_async16(sB + s * STAGE_B + off,
                       Bg + (size_t)(n0 + r) * 1024 + kt * 64 + lg * 8);
        }
        cp_commit();
    };

    const int arow  = wr + (lane & 7) + 8 * ((lane >> 3) & 1);
    const int kha   = lane >> 4;
    const int brow0 = wc + (lane & 7) + 8 * (lane >> 4);
    const int khb   = (lane >> 3) & 1;

    float acc[4][4][4];
#pragma unroll
    for (int mi = 0; mi < 4; mi++)
#pragma unroll
        for (int ni = 0; ni < 4; ni++)
#pragma unroll
            for (int r = 0; r < 4; r++) acc[mi][ni][r] = 0.0f;

    issue(0);
    issue(1);

    for (int kt = 0; kt < GKT; kt++) {
        if (kt + 1 < GKT) cp_wait<1>(); else cp_wait<0>();
        __syncthreads();
        if (kt + 2 < GKT) issue(kt + 2);

        const int s = kt % 3;
        const uint32_t aS = sA + s * STAGE_B;
        const uint32_t bS = sB + s * STAGE_B;

#pragma unroll
        for (int kk = 0; kk < 4; kk++) {
            uint32_t af[4][4];
#pragma unroll
            for (int mi = 0; mi < 4; mi++) {
                int r = arow + mi * 16;
                uint32_t addr = aS + r * 128 +
                                ((((kk << 1) | kha) ^ (r & 7)) << 4);
                ldsm_x4(af[mi], addr);
            }
            uint32_t bf[4][2];
#pragma unroll
            for (int p = 0; p < 2; p++) {
                int r = brow0 + p * 16;
                uint32_t addr = bS + r * 128 +
                                ((((kk << 1) | khb) ^ (r & 7)) << 4);
                uint32_t d[4];
                ldsm_x4(d, addr);
                bf[2 * p][0] = d[0]; bf[2 * p][1] = d[1];
                bf[2 * p + 1][0] = d[2]; bf[2 * p + 1][1] = d[3];
            }
#pragma unroll
            for (int mi = 0; mi < 4; mi++)
#pragma unroll
                for (int ni = 0; ni < 4; ni++)
                    mma_f16(acc[mi][ni], af[mi], bf[ni], acc[mi][ni]);
        }
    }

    // Epilogue (vectorized: col, col+1 are adjacent; col is even)
    const int g  = lane >> 2;
    const int tg = lane & 3;
#pragma unroll
    for (int mi = 0; mi < 4; mi++) {
        const int row0 = m0 + wr + mi * 16 + g;
        const int row1 = row0 + 8;
#pragma unroll
        for (int ni = 0; ni < 4; ni++) {
            const int col = n0 + wc + ni * 8 + tg * 2;
            const float b0 = __ldg(&bias[col]);
            const float b1 = __ldg(&bias[col + 1]);
            float v00 = acc[mi][ni][0] + b0;   // row0, col
            float v01 = acc[mi][ni][1] + b1;   // row0, col+1
            float v10 = acc[mi][ni][2] + b0;   // row1, col
            float v11 = acc[mi][ni][3] + b1;   // row1, col+1
            if (MODE == 0) {
                const int which = col >> 10;            // same for col+1
                const int rr = col & (C_ - 1);
                const int h = rr >> 6;
                const int d0 = rr & 63;
                const int b0i = row0 >> 11;
                const int t0 = row0 & (T_ - 1);
                const int t1 = row1 & (T_ - 1);
                const size_t bhh = (size_t)(b0i * H_ + h);
                if (which == 2) {
                    // vt[B,H,D,T]: adjacent cols -> different rows, scalar
                    __half* vt = g_vt16 + (bhh * D_ + d0) * T_;
                    vt[t0]      = __float2half_rn(v00);
                    vt[T_ + t0] = __float2half_rn(v01);
                    vt[t1]      = __float2half_rn(v10);
                    vt[T_ + t1] = __float2half_rn(v11);
                } else {
                    __half* dst = (which == 0) ? g_q16 : g_k16;
                    __half* p0 = dst + (bhh * T_ + t0) * D_ + d0;
                    __half* p1 = dst + (bhh * T_ + t1) * D_ + d0;
                    *(__half2*)p0 = __floats2half2_rn(v00, v01);
                    *(__half2*)p1 = __floats2half2_rn(v10, v11);
                }
            } else {
                *(float2*)&Cout[(size_t)row0 * N + col] = make_float2(v00, v01);
                *(float2*)&Cout[(size_t)row1 * N + col] = make_float2(v10, v11);
            }
        }
    }
}

// ---------------------------------------------------------------------------
// Flash attention body (causal), fp16 mma, BQ=128 BKV=64, 256 threads
// (8 warps, one 16-row q slab each). FA2: P in registers. K/Vt 3-stage
// cp.async ring, 1 sync/iter. Softmax fp32 base-2.
// ---------------------------------------------------------------------------
#define AQB 16384                        // Q: 128 rows x 128B
#define AKV 8192                         // K/Vt tile: 64 rows x 128B
#define AQ_OFF 0
#define AK_OFF AQB                       // + s*AKV   (3 stages)
#define AV_OFF (AQB + 3 * AKV)           // + s*AKV   (3 stages)

__device__ __forceinline__ void attn_body(char* smc, int b, int h, int qi)
{
    const uint32_t sQ = smem_u32(smc);
    const int bh  = b * H_ + h;
    const int tid = threadIdx.x;
    const int lane = tid & 31;
    const int wid  = tid >> 5;
    const int g    = lane >> 2;
    const int tg   = lane & 3;

    const __half* Qg  = g_q16  + ((size_t)bh * T_ + qi * 128) * D_;
    const __half* Kg  = g_k16  + (size_t)bh * T_ * D_;
    const __half* Vtg = g_vt16 + (size_t)bh * D_ * T_;

    // Q tile (128x64 halves) -> swizzled smem
#pragma unroll
    for (int it = 0; it < 4; it++) {
        int i = tid + it * 256;
        int r = i >> 3, gg = i & 7;
        uint4 v = *(const uint4*)&Qg[r * 64 + gg * 8];
        *(uint4*)(smc + r * 128 + ((gg ^ (r & 7)) << 4)) = v;
    }

    auto issue = [&](int j) {
        const int s = j % 3;
#pragma unroll
        for (int it = 0; it < 2; it++) {
            int i = tid + it * 256;
            int r = i >> 3, gg = i & 7;
            uint32_t sw = r * 128 + ((gg ^ (r & 7)) << 4);
            cp_async16(sQ + AK_OFF + s * AKV + sw,
                       Kg + ((size_t)j * 64 + r) * 64 + gg * 8);
            cp_async16(sQ + AV_OFF + s * AKV + sw,
                       Vtg + (size_t)r * T_ + j * 64 + gg * 8);
        }
        cp_commit();
    };

    const int jmax = 2 * qi + 1;
    issue(0);
    issue(1);

    // fragment lane constants
    const int qrow = wid * 16 + (lane & 7) + 8 * ((lane >> 3) & 1);
    const int khq  = lane >> 4;
    const int qxk  = qrow & 7;
    const uint32_t qbase = sQ + AQ_OFF + qrow * 128;
    const int brow = (lane & 7) + 8 * (lane >> 4);    // + p*16
    const int khb  = (lane >> 3) & 1;

    float O[8][4];
#pragma unroll
    for (int ni = 0; ni < 8; ni++)
#pragma unroll
        for (int r = 0; r < 4; r++) O[ni][r] = 0.0f;
    float mrow0 = -1e30f, mrow1 = -1e30f;
    float lrow0 = 0.0f,   lrow1 = 0.0f;

    const int rloc = wid * 16 + g;
    const float scale = 0.125f * 1.4426950408889634f;   // 1/sqrt(D) * log2(e)

    for (int j = 0; j <= jmax; j++) {
        const int s = j % 3;
        if (j < jmax) cp_wait<1>(); else cp_wait<0>();
        __syncthreads();
        if (j + 2 <= jmax) issue(j + 2);

        const uint32_t kS = sQ + AK_OFF + s * AKV;
        const uint32_t vS = sQ + AV_OFF + s * AKV;

        // S = Q K^T  (fp32 accum)
        float sfr[8][4];
#pragma unroll
        for (int ni = 0; ni < 8; ni++)
#pragma unroll
            for (int r = 0; r < 4; r++) sfr[ni][r] = 0.0f;

#pragma unroll
        for (int kk = 0; kk < 4; kk++) {
            uint32_t af[4];
            ldsm_x4(af, qbase + ((((kk << 1) | khq) ^ qxk) << 4));
            uint32_t bf[8][2];
#pragma unroll
            for (int p = 0; p < 4; p++) {
                int r = brow + p * 16;
                uint32_t d[4];
                ldsm_x4(d, kS + r * 128 + ((((kk << 1) | khb) ^ (r & 7)) << 4));
                bf[2 * p][0] = d[0]; bf[2 * p][1] = d[1];
                bf[2 * p + 1][0] = d[2]; bf[2 * p + 1][1] = d[3];
            }
#pragma unroll
            for (int ni = 0; ni < 8; ni++)
                mma_f16(sfr[ni], af, bf[ni], sfr[ni]);
        }

        // Scale (base-2) + causal mask (last two kv tiles straddle diagonal)
        const bool diag = (j >= 2 * qi);
        const int rowg0 = qi * 128 + rloc;
        const int rowg1 = rowg0 + 8;
#pragma unroll
        for (int ni = 0; ni < 8; ni++) {
#pragma unroll
            for (int r = 0; r < 4; r++) {
                float sv = sfr[ni][r] * scale;
                if (diag) {
                    int colg = j * 64 + ni * 8 + tg * 2 + (r & 1);
                    int rowg = (r >> 1) ? rowg1 : rowg0;
                    if (colg > rowg) sv = -1e30f;
                }
                sfr[ni][r] = sv;
            }
        }

        // Online softmax (base-2; two rows per thread)
        float mx0 = -1e30f, mx1 = -1e30f;
#pragma unroll
        for (int ni = 0; ni < 8; ni++) {
            mx0 = fmaxf(mx0, fmaxf(sfr[ni][0], sfr[ni][1]));
            mx1 = fmaxf(mx1, fmaxf(sfr[ni][2], sfr[ni][3]));
        }
        mx0 = fmaxf(mx0, __shfl_xor_sync(0xffffffffu, mx0, 1));
        mx0 = fmaxf(mx0, __shfl_xor_sync(0xffffffffu, mx0, 2));
        mx1 = fmaxf(mx1, __shfl_xor_sync(0xffffffffu, mx1, 1));
        mx1 = fmaxf(mx1, __shfl_xor_sync(0xffffffffu, mx1, 2));

        float mn0 = fmaxf(mrow0, mx0);
        float mn1 = fmaxf(mrow1, mx1);
        float a0 = ex2f(mrow0 - mn0);
        float a1 = ex2f(mrow1 - mn1);

        float rs0 = 0.0f, rs1 = 0.0f;
#pragma unroll
        for (int ni = 0; ni < 8; ni++) {
            float p0 = ex2f(sfr[ni][0] - mn0); sfr[ni][0] = p0; rs0 += p0;
            float p1 = ex2f(sfr[ni][1] - mn0); sfr[ni][1] = p1; rs0 += p1;
            float p2 = ex2f(sfr[ni][2] - mn1); sfr[ni][2] = p2; rs1 += p2;
            float p3 = ex2f(sfr[ni][3] - mn1); sfr[ni][3] = p3; rs1 += p3;
        }
        rs0 += __shfl_xor_sync(0xffffffffu, rs0, 1);
        rs0 += __shfl_xor_sync(0xffffffffu, rs0, 2);
        rs1 += __shfl_xor_sync(0xffffffffu, rs1, 1);
        rs1 += __shfl_xor_sync(0xffffffffu, rs1, 2);

        lrow0 = lrow0 * a0 + rs0;
        lrow1 = lrow1 * a1 + rs1;
        mrow0 = mn0;
        mrow1 = mn1;

#pragma unroll
        for (int ni = 0; ni < 8; ni++) {
            O[ni][0] *= a0; O[ni][1] *= a0;
            O[ni][2] *= a1; O[ni][3] *= a1;
        }

        // O += P @ V : FA2 repack — S accumulator fragment IS the PV
        // A-operand fragment.
#pragma unroll
        for (int kk = 0; kk < 4; kk++) {
            uint32_t af[4];
            af[0] = packh2(sfr[2 * kk    ][0], sfr[2 * kk    ][1]);
            af[1] = packh2(sfr[2 * kk    ][2], sfr[2 * kk    ][3]);
            af[2] = packh2(sfr[2 * kk + 1][0], sfr[2 * kk + 1][1]);
            af[3] = packh2(sfr[2 * kk + 1][2], sfr[2 * kk + 1][3]);
            uint32_t bf[8][2];
#pragma unroll
            for (int p = 0; p < 4; p++) {
                int r = brow + p * 16;
                uint32_t d[4];
                ldsm_x4(d, vS + r * 128 + ((((kk << 1) | khb) ^ (r & 7)) << 4));
                bf[2 * p][0] = d[0]; bf[2 * p][1] = d[1];
                bf[2 * p + 1][0] = d[2]; bf[2 * p + 1][1] = d[3];
            }
#pragma unroll
            for (int ni = 0; ni < 8; ni++)
                mma_f16(O[ni], af, bf[ni], O[ni]);
        }
    }

    // Epilogue: O /= l, convert to half, write [B,T,H,D]
    float il0 = 1.0f / lrow0;
    float il1 = 1.0f / lrow1;
    int t0 = qi * 128 + rloc;
#pragma unroll
    for (int ni = 0; ni < 8; ni++) {
        int d = ni * 8 + tg * 2;
        size_t base0 = ((size_t)(b * T_ + t0    ) * H_ + h) * D_ + d;
        size_t base1 = ((size_t)(b * T_ + t0 + 8) * H_ + h) * D_ + d;
        *(__half2*)&g_y16[base0] = __floats2half2_rn(O[ni][0] * il0, O[ni][1] * il0);
        *(__half2*)&g_y16[base1] = __floats2half2_rn(O[ni][2] * il1, O[ni][3] * il1);
    }
}

// ---------------------------------------------------------------------------
// Mega kernel: grid-level pipeline, PHASE-BLOCKED ordering (R11 schedule).
//   bids [0,1536):    qkv gemm tiles, row-groups ascending -> cnt0[rt]++
//   bids [1536,2560): attention (qi ascending), gated on cnt0 -> cnt1[grp]++
//   bids [2560,3072): out-proj tiles, gated on cnt1[grp]==16
// Consumers only wait on strictly-lower-bid producers.
// ---------------------------------------------------------------------------
#define MEGA_GRID 3072

__global__ __launch_bounds__(256, 2) void mega_kernel(
    const float* __restrict__ bqkv, const float* __restrict__ bout,
    float* __restrict__ out)
{
    extern __shared__ char smc[];
    const int bid = blockIdx.x;

    if (bid < 1536) {
        // ---- QKV GEMM tile ----
        int rt_pos = bid / 24;               // 0..63, ascending t-group
        int ct = bid - rt_pos * 24;          // 0..23
        int qi_r = rt_pos >> 2;              // t-tile within batch
        int b = rt_pos & 3;
        int rt = b * 16 + qi_r;              // row-tile id (= cnt0 index)
        gemm_body<0>(smc, g_x16, g_wqkvT16, bqkv, nullptr, 3 * C_,
                     rt * 128, ct * 128);
        __syncthreads();
        if (threadIdx.x == 0) {
            __threadfence();
            atomicAdd(&g_cnt0[rt], 1);
        }
    } else if (bid < 2560) {
        // ---- attention ----
        int idx = bid - 1536;
        int qi = idx >> 6;                   // ascending qi
        int bh = idx & 63;
        int b = bh >> 4;
        int h = bh & 15;
        if (threadIdx.x == 0) {
            for (int i = 0; i <= qi; i++)
                while (atomicAdd(&g_cnt0[b * 16 + i], 0) < 24) __nanosleep(128);
        }
        __syncthreads();
        attn_body(smc, b, h, qi);
        __syncthreads();
        if (threadIdx.x == 0) {
            __threadfence();
            atomicAdd(&g_cnt1[b * 16 + qi], 1);
        }
    } else {
        // ---- out-projection tile ----
        int idx = bid - 2560;
        int qi_g = idx >> 5;                 // ascending qi
        int b = (idx >> 3) & 3;
        int c = idx & 7;
        int grp = b * 16 + qi_g;
        if (threadIdx.x == 0) {
            while (atomicAdd(&g_cnt1[grp], 0) < 16) __nanosleep(128);
        }
        __syncthreads();
        gemm_body<1>(smc, g_y16, g_woutT16, bout, out, C_,
                     grp * 128, c * 128);
    }
}

// ---------------------------------------------------------------------------
// Launch
// ---------------------------------------------------------------------------
extern "C" void kernel_launch(void* const* d_in, const int* in_sizes, int n_in,
                              void* d_out, int out_size)
{
    const float* x     = (const float*)d_in[0];
    const float* Wqkv  = (const float*)d_in[1];
    const float* bqkv  = (const float*)d_in[2];
    const float* Wout  = (const float*)d_in[3];
    const float* bout  = (const float*)d_in[4];
    float* out = (float*)d_out;

    cudaFuncSetAttribute(mega_kernel,
                         cudaFuncAttributeMaxDynamicSharedMemorySize, GEMM_SMEM);

    // 0) prep: x -> half, W^T -> half, zero flags (one launch)
    prep_kernel<<<PREP_GRID, 256>>>(x, Wqkv, Wout);

    // 1) fused qkv-gemm -> attention -> out-proj pipeline, one launch
    mega_kernel<<<MEGA_GRID, 256, GEMM_SMEM>>>(bqkv, bout, out);
}

// round 14
// speedup vs baseline: 1.3057x; 1.0271x over previous
#include <cuda_runtime.h>
#include <cuda_fp16.h>
#include <cstdint>
#include <math.h>

// Problem constants
#define B_ 4
#define T_ 2048
#define C_ 1024
#define H_ 16
#define D_ 64
#define BH_ (B_ * H_)

// softmax scale folded into q: 1/sqrt(D) * log2(e)
#define QSCALE 0.18033688011112042f

// Scratch (device globals -- no allocation allowed)
__device__ __half g_q16[BH_ * T_ * D_];     // [B,H,T,D], pre-scaled by QSCALE
__device__ __half g_k16[BH_ * T_ * D_];     // [B,H,T,D]
__device__ __half g_vt16[BH_ * D_ * T_];    // [B,H,D,T]  (V transposed)
__device__ __half g_y16[B_ * T_ * C_];      // [B,T,C]
__device__ __half g_x16[B_ * T_ * C_];      // x -> half
__device__ __half g_wqkvT16[3 * C_ * C_];   // [3C, C] = W_qkv^T
__device__ __half g_woutT16[C_ * C_];       // [C, C]  = W_out^T

// Flag counters for the in-kernel pipeline (zeroed by prep each call)
__device__ int g_cnt0[64];   // per qkv row-tile: col-tiles done (24 = ready)
__device__ int g_cnt1[64];   // per (b,qi) group: heads done (16 = ready)

// ---------------------------------------------------------------------------
// Helpers
// ---------------------------------------------------------------------------
__device__ __forceinline__ uint32_t smem_u32(const void* p) {
    return (uint32_t)__cvta_generic_to_shared(p);
}

__device__ __forceinline__ float ex2f(float x) {
    float y;
    asm("ex2.approx.f32 %0, %1;" : "=f"(y) : "f"(x));
    return y;
}

__device__ __forceinline__ uint32_t packh2(float a, float b) {
    __half2 h = __floats2half2_rn(a, b);
    return *(uint32_t*)&h;
}

__device__ __forceinline__ void mma_f16(float d[4], const uint32_t a[4],
                                        const uint32_t b[2], const float c[4]) {
    asm volatile(
        "mma.sync.aligned.m16n8k16.row.col.f32.f16.f16.f32 "
        "{%0,%1,%2,%3},{%4,%5,%6,%7},{%8,%9},{%10,%11,%12,%13};"
        : "=f"(d[0]), "=f"(d[1]), "=f"(d[2]), "=f"(d[3])
        : "r"(a[0]), "r"(a[1]), "r"(a[2]), "r"(a[3]),
          "r"(b[0]), "r"(b[1]),
          "f"(c[0]), "f"(c[1]), "f"(c[2]), "f"(c[3]));
}

__device__ __forceinline__ void ldsm_x4(uint32_t d[4], uint32_t saddr) {
    asm volatile(
        "ldmatrix.sync.aligned.m8n8.x4.shared.b16 {%0,%1,%2,%3}, [%4];"
        : "=r"(d[0]), "=r"(d[1]), "=r"(d[2]), "=r"(d[3]) : "r"(saddr));
}

__device__ __forceinline__ void cp_async16(uint32_t dst, const void* src) {
    asm volatile("cp.async.cg.shared.global [%0], [%1], 16;"
                 :: "r"(dst), "l"(src) : "memory");
}
__device__ __forceinline__ void cp_commit() {
    asm volatile("cp.async.commit_group;" ::: "memory");
}
template <int N>
__device__ __forceinline__ void cp_wait() {
    asm volatile("cp.async.wait_group %0;" :: "n"(N) : "memory");
}

// ---------------------------------------------------------------------------
// Unified prep kernel (one launch):
//   bids [0,8192):      x -> half (2M float4)
//   bids [8192,11264):  transpose Wqkv [1024,3072] -> [3072,1024] half
//   bids [11264,12288): transpose Wout [1024,1024] -> [1024,1024] half
//   bid 0 also zeroes the pipeline flags.
// ---------------------------------------------------------------------------
#define PREP_GRID 12288

__global__ __launch_bounds__(256) void prep_kernel(
    const float* __restrict__ x,
    const float* __restrict__ Wqkv,
    const float* __restrict__ Wout)
{
    __shared__ float t[32][33];
    const int bid = blockIdx.x;
    const int tid = threadIdx.x;

    if (bid == 0 && tid < 64) {
        g_cnt0[tid] = 0;
        g_cnt1[tid] = 0;
    }

    if (bid < 8192) {
        int i = bid * 256 + tid;
        float4 v = ((const float4*)x)[i];
        __half2* o = (__half2*)(g_x16 + (size_t)i * 4);
        o[0] = __floats2half2_rn(v.x, v.y);
        o[1] = __floats2half2_rn(v.z, v.w);
        return;
    }

    // transpose: in [R=1024, Ccols], out [Ccols, 1024] half
    const float* in;
    __half* outp;
    int Ccols, bx, by;
    if (bid < 11264) {
        int id = bid - 8192;           // 96 x 32 tiles
        in = Wqkv; outp = g_wqkvT16; Ccols = 3072;
        bx = (id % 96) * 32; by = (id / 96) * 32;
    } else {
        int id = bid - 11264;          // 32 x 32 tiles
        in = Wout; outp = g_woutT16; Ccols = 1024;
        bx = (id % 32) * 32; by = (id / 32) * 32;
    }
    const int xL = tid & 31;
    const int yL = tid >> 5;           // 0..7
#pragma unroll
    for (int j = 0; j < 32; j += 8)
        t[yL + j][xL] = in[(size_t)(by + yL + j) * Ccols + bx + xL];
    __syncthreads();
#pragma unroll
    for (int j = 0; j < 32; j += 8)
        outp[(size_t)(bx + yL + j) * 1024 + by + xL] = __float2half_rn(t[xL][yL + j]);
}

// ---------------------------------------------------------------------------
// FP16 GEMM body: C[m0..][N] tile = A @ Bt^T + bias (fp32 acc)
// BM=128 BN=128 BK=64 halves, 256 threads (8 warps 2x4), warp tile 64x32.
// cp.async 3-stage, 1 sync/iter, ldmatrix both operands.
// MODE 0: convert to half + scatter q (scaled by QSCALE) / k (BHTD, half2)
//         and vt (BHDT, scalar).
// MODE 1: fp32 row-major store (float2) + bias.
// ---------------------------------------------------------------------------
#define GKT 16                    // k-tiles (K=1024 / 64)
#define STAGE_B 16384             // 128 rows x 128B
#define GEMM_SMEM (6 * STAGE_B)   // 3 stages x (A+B) = 98304

template <int MODE>
__device__ __forceinline__ void gemm_body(
    char* smem, const __half* __restrict__ Ag, const __half* __restrict__ Bg,
    const float* __restrict__ bias, float* __restrict__ Cout, int N,
    int m0, int n0)
{
    const uint32_t sA = smem_u32(smem);
    const uint32_t sB = sA + 3 * STAGE_B;

    const int tid  = threadIdx.x;
    const int lane = tid & 31;
    const int wid  = tid >> 5;
    const int wr   = (wid >> 2) * 64;
    const int wc   = (wid & 3) * 32;

    const int lr = tid >> 3;      // + i*32
    const int lg = tid & 7;       // 16B group (8 halves)

    auto issue = [&](int kt) {
        const int s = kt % 3;
#pragma unroll
        for (int i = 0; i < 4; i++) {
            int r = lr + i * 32;
            uint32_t off = r * 128 + ((lg ^ (r & 7)) << 4);
            cp_async16(sA + s * STAGE_B + off,
                       Ag + (size_t)(m0 + r) * 1024 + kt * 64 + lg * 8);
            cp_async16(sB + s * STAGE_B + off,
                       Bg + (size_t)(n0 + r) * 1024 + kt * 64 + lg * 8);
        }
        cp_commit();
    };

    const int arow  = wr + (lane & 7) + 8 * ((lane >> 3) & 1);
    const int kha   = lane >> 4;
    const int brow0 = wc + (lane & 7) + 8 * (lane >> 4);
    const int khb   = (lane >> 3) & 1;

    float acc[4][4][4];
#pragma unroll
    for (int mi = 0; mi < 4; mi++)
#pragma unroll
        for (int ni = 0; ni < 4; ni++)
#pragma unroll
            for (int r = 0; r < 4; r++) acc[mi][ni][r] = 0.0f;

    issue(0);
    issue(1);

    for (int kt = 0; kt < GKT; kt++) {
        if (kt + 1 < GKT) cp_wait<1>(); else cp_wait<0>();
        __syncthreads();
        if (kt + 2 < GKT) issue(kt + 2);

        const int s = kt % 3;
        const uint32_t aS = sA + s * STAGE_B;
        const uint32_t bS = sB + s * STAGE_B;

#pragma unroll
        for (int kk = 0; kk < 4; kk++) {
            uint32_t af[4][4];
#pragma unroll
            for (int mi = 0; mi < 4; mi++) {
                int r = arow + mi * 16;
                uint32_t addr = aS + r * 128 +
                                ((((kk << 1) | kha) ^ (r & 7)) << 4);
                ldsm_x4(af[mi], addr);
            }
            uint32_t bf[4][2];
#pragma unroll
            for (int p = 0; p < 2; p++) {
                int r = brow0 + p * 16;
                uint32_t addr = bS + r * 128 +
                                ((((kk << 1) | khb) ^ (r & 7)) << 4);
                uint32_t d[4];
                ldsm_x4(d, addr);
                bf[2 * p][0] = d[0]; bf[2 * p][1] = d[1];
                bf[2 * p + 1][0] = d[2]; bf[2 * p + 1][1] = d[3];
            }
#pragma unroll
            for (int mi = 0; mi < 4; mi++)
#pragma unroll
                for (int ni = 0; ni < 4; ni++)
                    mma_f16(acc[mi][ni], af[mi], bf[ni], acc[mi][ni]);
        }
    }

    // Epilogue (vectorized: col, col+1 are adjacent; col is even)
    const int g  = lane >> 2;
    const int tg = lane & 3;
#pragma unroll
    for (int mi = 0; mi < 4; mi++) {
        const int row0 = m0 + wr + mi * 16 + g;
        const int row1 = row0 + 8;
#pragma unroll
        for (int ni = 0; ni < 4; ni++) {
            const int col = n0 + wc + ni * 8 + tg * 2;
            const float b0 = __ldg(&bias[col]);
            const float b1 = __ldg(&bias[col + 1]);
            float v00 = acc[mi][ni][0] + b0;   // row0, col
            float v01 = acc[mi][ni][1] + b1;   // row0, col+1
            float v10 = acc[mi][ni][2] + b0;   // row1, col
            float v11 = acc[mi][ni][3] + b1;   // row1, col+1
            if (MODE == 0) {
                const int which = col >> 10;            // same for col+1
                const int rr = col & (C_ - 1);
                const int h = rr >> 6;
                const int d0 = rr & 63;
                const int b0i = row0 >> 11;
                const int t0 = row0 & (T_ - 1);
                const int t1 = row1 & (T_ - 1);
                const size_t bhh = (size_t)(b0i * H_ + h);
                if (which == 2) {
                    // vt[B,H,D,T]: adjacent cols -> different rows, scalar
                    __half* vt = g_vt16 + (bhh * D_ + d0) * T_;
                    vt[t0]      = __float2half_rn(v00);
                    vt[T_ + t0] = __float2half_rn(v01);
                    vt[t1]      = __float2half_rn(v10);
                    vt[T_ + t1] = __float2half_rn(v11);
                } else {
                    if (which == 0) {
                        v00 *= QSCALE; v01 *= QSCALE;
                        v10 *= QSCALE; v11 *= QSCALE;
                    }
                    __half* dst = (which == 0) ? g_q16 : g_k16;
                    __half* p0 = dst + (bhh * T_ + t0) * D_ + d0;
                    __half* p1 = dst + (bhh * T_ + t1) * D_ + d0;
                    *(__half2*)p0 = __floats2half2_rn(v00, v01);
                    *(__half2*)p1 = __floats2half2_rn(v10, v11);
                }
            } else {
                *(float2*)&Cout[(size_t)row0 * N + col] = make_float2(v00, v01);
                *(float2*)&Cout[(size_t)row1 * N + col] = make_float2(v10, v11);
            }
        }
    }
}

// ---------------------------------------------------------------------------
// Flash attention body (causal), fp16 mma, BQ=128 BKV=64, 256 threads
// (8 warps, one 16-row q slab each). FA2: P in registers. l via ones-column
// MMA (no sum reduction). K/Vt 3-stage cp.async ring, 1 sync/iter.
// Fully-masked warps skip compute on the last diagonal tile.
// ---------------------------------------------------------------------------
#define AQB 16384                        // Q: 128 rows x 128B
#define AKV 8192                         // K/Vt tile: 64 rows x 128B
#define AQ_OFF 0
#define AK_OFF AQB                       // + s*AKV   (3 stages)
#define AV_OFF (AQB + 3 * AKV)           // + s*AKV   (3 stages)

__device__ __forceinline__ void attn_body(char* smc, int b, int h, int qi)
{
    const uint32_t sQ = smem_u32(smc);
    const int bh  = b * H_ + h;
    const int tid = threadIdx.x;
    const int lane = tid & 31;
    const int wid  = tid >> 5;
    const int g    = lane >> 2;
    const int tg   = lane & 3;

    const __half* Qg  = g_q16  + ((size_t)bh * T_ + qi * 128) * D_;
    const __half* Kg  = g_k16  + (size_t)bh * T_ * D_;
    const __half* Vtg = g_vt16 + (size_t)bh * D_ * T_;

    // Q tile (128x64 halves) -> swizzled smem
#pragma unroll
    for (int it = 0; it < 4; it++) {
        int i = tid + it * 256;
        int r = i >> 3, gg = i & 7;
        uint4 v = *(const uint4*)&Qg[r * 64 + gg * 8];
        *(uint4*)(smc + r * 128 + ((gg ^ (r & 7)) << 4)) = v;
    }

    auto issue = [&](int j) {
        const int s = j % 3;
#pragma unroll
        for (int it = 0; it < 2; it++) {
            int i = tid + it * 256;
            int r = i >> 3, gg = i & 7;
            uint32_t sw = r * 128 + ((gg ^ (r & 7)) << 4);
            cp_async16(sQ + AK_OFF + s * AKV + sw,
                       Kg + ((size_t)j * 64 + r) * 64 + gg * 8);
            cp_async16(sQ + AV_OFF + s * AKV + sw,
                       Vtg + (size_t)r * T_ + j * 64 + gg * 8);
        }
        cp_commit();
    };

    const int jmax = 2 * qi + 1;
    issue(0);
    issue(1);

    // fragment lane constants
    const int qrow = wid * 16 + (lane & 7) + 8 * ((lane >> 3) & 1);
    const int khq  = lane >> 4;
    const int qxk  = qrow & 7;
    const uint32_t qbase = sQ + AQ_OFF + qrow * 128;
    const int brow = (lane & 7) + 8 * (lane >> 4);    // + p*16
    const int khb  = (lane >> 3) & 1;

    // ones b-fragment for row-sum MMA (1.0h packed twice)
    const uint32_t bf_ones[2] = {0x3C003C00u, 0x3C003C00u};

    float O[8][4];
#pragma unroll
    for (int ni = 0; ni < 8; ni++)
#pragma unroll
        for (int r = 0; r < 4; r++) O[ni][r] = 0.0f;
    float lacc[4] = {0.0f, 0.0f, 0.0f, 0.0f};   // l in cols (duplicated)
    float mrow0 = -1e30f, mrow1 = -1e30f;

    const int rloc = wid * 16 + g;
    const int wtop = qi * 128 + wid * 16 + 15;   // warp's highest global row

    for (int j = 0; j <= jmax; j++) {
        const int s = j % 3;
        if (j < jmax) cp_wait<1>(); else cp_wait<0>();
        __syncthreads();
        if (j + 2 <= jmax) issue(j + 2);

        // Fully-masked warp on this tile? (all rows < first kv col)
        if (wtop < j * 64) continue;

        const uint32_t kS = sQ + AK_OFF + s * AKV;
        const uint32_t vS = sQ + AV_OFF + s * AKV;

        // S = Q K^T  (fp32 accum; scale pre-folded into q)
        float sfr[8][4];
#pragma unroll
        for (int ni = 0; ni < 8; ni++)
#pragma unroll
            for (int r = 0; r < 4; r++) sfr[ni][r] = 0.0f;

#pragma unroll
        for (int kk = 0; kk < 4; kk++) {
            uint32_t af[4];
            ldsm_x4(af, qbase + ((((kk << 1) | khq) ^ qxk) << 4));
            uint32_t bf[8][2];
#pragma unroll
            for (int p = 0; p < 4; p++) {
                int r = brow + p * 16;
                uint32_t d[4];
                ldsm_x4(d, kS + r * 128 + ((((kk << 1) | khb) ^ (r & 7)) << 4));
                bf[2 * p][0] = d[0]; bf[2 * p][1] = d[1];
                bf[2 * p + 1][0] = d[2]; bf[2 * p + 1][1] = d[3];
            }
#pragma unroll
            for (int ni = 0; ni < 8; ni++)
                mma_f16(sfr[ni], af, bf[ni], sfr[ni]);
        }

        // Causal mask (last two kv tiles straddle diagonal)
        const bool diag = (j >= 2 * qi);
        const int rowg0 = qi * 128 + rloc;
        const int rowg1 = rowg0 + 8;
        if (diag) {
#pragma unroll
            for (int ni = 0; ni < 8; ni++) {
#pragma unroll
                for (int r = 0; r < 4; r++) {
                    int colg = j * 64 + ni * 8 + tg * 2 + (r & 1);
                    int rowg = (r >> 1) ? rowg1 : rowg0;
                    if (colg > rowg) sfr[ni][r] = -1e30f;
                }
            }
        }

        // Online softmax max (two rows per thread)
        float mx0 = -1e30f, mx1 = -1e30f;
#pragma unroll
        for (int ni = 0; ni < 8; ni++) {
            mx0 = fmaxf(mx0, fmaxf(sfr[ni][0], sfr[ni][1]));
            mx1 = fmaxf(mx1, fmaxf(sfr[ni][2], sfr[ni][3]));
        }
        mx0 = fmaxf(mx0, __shfl_xor_sync(0xffffffffu, mx0, 1));
        mx0 = fmaxf(mx0, __shfl_xor_sync(0xffffffffu, mx0, 2));
        mx1 = fmaxf(mx1, __shfl_xor_sync(0xffffffffu, mx1, 1));
        mx1 = fmaxf(mx1, __shfl_xor_sync(0xffffffffu, mx1, 2));

        float mn0 = fmaxf(mrow0, mx0);
        float mn1 = fmaxf(mrow1, mx1);
        float a0 = ex2f(mrow0 - mn0);
        float a1 = ex2f(mrow1 - mn1);
        mrow0 = mn0;
        mrow1 = mn1;

        // P = 2^(s - m) (no explicit sum: l comes from ones-MMA)
#pragma unroll
        for (int ni = 0; ni < 8; ni++) {
            sfr[ni][0] = ex2f(sfr[ni][0] - mn0);
            sfr[ni][1] = ex2f(sfr[ni][1] - mn0);
            sfr[ni][2] = ex2f(sfr[ni][2] - mn1);
            sfr[ni][3] = ex2f(sfr[ni][3] - mn1);
        }

        // Rescale O and l
#pragma unroll
        for (int ni = 0; ni < 8; ni++) {
            O[ni][0] *= a0; O[ni][1] *= a0;
            O[ni][2] *= a1; O[ni][3] *= a1;
        }
        lacc[0] *= a0; lacc[1] *= a0;
        lacc[2] *= a1; lacc[3] *= a1;

        // O += P @ V ; l += P @ 1 (FA2 repack: S accumulator fragment IS the
        // PV A-operand fragment)
#pragma unroll
        for (int kk = 0; kk < 4; kk++) {
            uint32_t af[4];
            af[0] = packh2(sfr[2 * kk    ][0], sfr[2 * kk    ][1]);
            af[1] = packh2(sfr[2 * kk    ][2], sfr[2 * kk    ][3]);
            af[2] = packh2(sfr[2 * kk + 1][0], sfr[2 * kk + 1][1]);
            af[3] = packh2(sfr[2 * kk + 1][2], sfr[2 * kk + 1][3]);
            uint32_t bf[8][2];
#pragma unroll
            for (int p = 0; p < 4; p++) {
                int r = brow + p * 16;
                uint32_t d[4];
                ldsm_x4(d, vS + r * 128 + ((((kk << 1) | khb) ^ (r & 7)) << 4));
                bf[2 * p][0] = d[0]; bf[2 * p][1] = d[1];
                bf[2 * p + 1][0] = d[2]; bf[2 * p + 1][1] = d[3];
            }
#pragma unroll
            for (int ni = 0; ni < 8; ni++)
                mma_f16(O[ni], af, bf[ni], O[ni]);
            mma_f16(lacc, af, bf_ones, lacc);
        }
    }

    // Epilogue: O /= l (l cols are duplicated; [0]=row g, [2]=row g+8)
    float il0 = 1.0f / lacc[0];
    float il1 = 1.0f / lacc[2];
    int t0 = qi * 128 + rloc;
#pragma unroll
    for (int ni = 0; ni < 8; ni++) {
        int d = ni * 8 + tg * 2;
        size_t base0 = ((size_t)(b * T_ + t0    ) * H_ + h) * D_ + d;
        size_t base1 = ((size_t)(b * T_ + t0 + 8) * H_ + h) * D_ + d;
        *(__half2*)&g_y16[base0] = __floats2half2_rn(O[ni][0] * il0, O[ni][1] * il0);
        *(__half2*)&g_y16[base1] = __floats2half2_rn(O[ni][2] * il1, O[ni][3] * il1);
    }
}

// ---------------------------------------------------------------------------
// Mega kernel: grid-level pipeline, PHASE-BLOCKED ordering (R11 schedule).
//   bids [0,1536):    qkv gemm tiles, row-groups ascending -> cnt0[rt]++
//   bids [1536,2560): attention (qi ascending), gated on cnt0 -> cnt1[grp]++
//   bids [2560,3072): out-proj tiles, gated on cnt1[grp]==16
// Consumers only wait on strictly-lower-bid producers.
// ---------------------------------------------------------------------------
#define MEGA_GRID 3072

__global__ __launch_bounds__(256, 2) void mega_kernel(
    const float* __restrict__ bqkv, const float* __restrict__ bout,
    float* __restrict__ out)
{
    extern __shared__ char smc[];
    const int bid = blockIdx.x;

    if (bid < 1536) {
        // ---- QKV GEMM tile ----
        int rt_pos = bid / 24;               // 0..63, ascending t-group
        int ct = bid - rt_pos * 24;          // 0..23
        int qi_r = rt_pos >> 2;              // t-tile within batch
        int b = rt_pos & 3;
        int rt = b * 16 + qi_r;              // row-tile id (= cnt0 index)
        gemm_body<0>(smc, g_x16, g_wqkvT16, bqkv, nullptr, 3 * C_,
                     rt * 128, ct * 128);
        __syncthreads();
        if (threadIdx.x == 0) {
            __threadfence();
            atomicAdd(&g_cnt0[rt], 1);
        }
    } else if (bid < 2560) {
        // ---- attention ----
        int idx = bid - 1536;
        int qi = idx >> 6;                   // ascending qi
        int bh = idx & 63;
        int b = bh >> 4;
        int h = bh & 15;
        if (threadIdx.x == 0) {
            for (int i = 0; i <= qi; i++)
                while (atomicAdd(&g_cnt0[b * 16 + i], 0) < 24) __nanosleep(128);
        }
        __syncthreads();
        attn_body(smc, b, h, qi);
        __syncthreads();
        if (threadIdx.x == 0) {
            __threadfence();
            atomicAdd(&g_cnt1[b * 16 + qi], 1);
        }
    } else {
        // ---- out-projection tile ----
        int idx = bid - 2560;
        int qi_g = idx >> 5;                 // ascending qi
        int b = (idx >> 3) & 3;
        int c = idx & 7;
        int grp = b * 16 + qi_g;
        if (threadIdx.x == 0) {
            while (atomicAdd(&g_cnt1[grp], 0) < 16) __nanosleep(128);
        }
        __syncthreads();
        gemm_body<1>(smc, g_y16, g_woutT16, bout, out, C_,
                     grp * 128, c * 128);
    }
}

// ---------------------------------------------------------------------------
// Launch
// ---------------------------------------------------------------------------
extern "C" void kernel_launch(void* const* d_in, const int* in_sizes, int n_in,
                              void* d_out, int out_size)
{
    const float* x     = (const float*)d_in[0];
    const float* Wqkv  = (const float*)d_in[1];
    const float* bqkv  = (const float*)d_in[2];
    const float* Wout  = (const float*)d_in[3];
    const float* bout  = (const float*)d_in[4];
    float* out = (float*)d_out;

    cudaFuncSetAttribute(mega_kernel,
                         cudaFuncAttributeMaxDynamicSharedMemorySize, GEMM_SMEM);

    // 0) prep: x -> half, W^T -> half, zero flags (one launch)
    prep_kernel<<<PREP_GRID, 256>>>(x, Wqkv, Wout);

    // 1) fused qkv-gemm -> attention -> out-proj pipeline, one launch
    mega_kernel<<<MEGA_GRID, 256, GEMM_SMEM>>>(bqkv, bout, out);
}

// round 15
// speedup vs baseline: 1.3519x; 1.0355x over previous
#include <cuda_runtime.h>
#include <cuda_fp16.h>
#include <cstdint>
#include <math.h>

// Problem constants
#define B_ 4
#define T_ 2048
#define C_ 1024
#define H_ 16
#define D_ 64
#define BH_ (B_ * H_)

// softmax scale folded into q: 1/sqrt(D) * log2(e)
#define QSCALE 0.18033688011112042f

// Scratch (device globals -- no allocation allowed)
__device__ __half g_q16[BH_ * T_ * D_];     // [B,H,T,D], pre-scaled by QSCALE
__device__ __half g_k16[BH_ * T_ * D_];     // [B,H,T,D]
__device__ __half g_vt16[BH_ * D_ * T_];    // [B,H,D,T]  (V transposed)
__device__ __half g_y16[B_ * T_ * C_];      // [B,T,C]
__device__ __half g_x16[B_ * T_ * C_];      // x -> half
__device__ __half g_wqkvT16[3 * C_ * C_];   // [3C, C] = W_qkv^T
__device__ __half g_woutT16[C_ * C_];       // [C, C]  = W_out^T

// Flag counters for the in-kernel pipeline (zeroed by prep each call)
__device__ int g_cnt0[64];   // per qkv row-tile: col-tiles done (24 = ready)
__device__ int g_cnt1[64];   // per (b,qi) group: heads done (16 = ready)

// ---------------------------------------------------------------------------
// Helpers
// ---------------------------------------------------------------------------
__device__ __forceinline__ uint32_t smem_u32(const void* p) {
    return (uint32_t)__cvta_generic_to_shared(p);
}

__device__ __forceinline__ float ex2f(float x) {
    float y;
    asm("ex2.approx.f32 %0, %1;" : "=f"(y) : "f"(x));
    return y;
}

__device__ __forceinline__ uint32_t packh2(float a, float b) {
    __half2 h = __floats2half2_rn(a, b);
    return *(uint32_t*)&h;
}

// packed fp16x2 2^x (P is fp16-rounded immediately after anyway)
__device__ __forceinline__ uint32_t h2ex2(uint32_t x) {
    uint32_t y;
    asm("ex2.approx.f16x2 %0, %1;" : "=r"(y) : "r"(x));
    return y;
}

__device__ __forceinline__ void mma_f16(float d[4], const uint32_t a[4],
                                        const uint32_t b[2], const float c[4]) {
    asm volatile(
        "mma.sync.aligned.m16n8k16.row.col.f32.f16.f16.f32 "
        "{%0,%1,%2,%3},{%4,%5,%6,%7},{%8,%9},{%10,%11,%12,%13};"
        : "=f"(d[0]), "=f"(d[1]), "=f"(d[2]), "=f"(d[3])
        : "r"(a[0]), "r"(a[1]), "r"(a[2]), "r"(a[3]),
          "r"(b[0]), "r"(b[1]),
          "f"(c[0]), "f"(c[1]), "f"(c[2]), "f"(c[3]));
}

__device__ __forceinline__ void ldsm_x4(uint32_t d[4], uint32_t saddr) {
    asm volatile(
        "ldmatrix.sync.aligned.m8n8.x4.shared.b16 {%0,%1,%2,%3}, [%4];"
        : "=r"(d[0]), "=r"(d[1]), "=r"(d[2]), "=r"(d[3]) : "r"(saddr));
}

__device__ __forceinline__ void cp_async16(uint32_t dst, const void* src) {
    asm volatile("cp.async.cg.shared.global [%0], [%1], 16;"
                 :: "r"(dst), "l"(src) : "memory");
}
__device__ __forceinline__ void cp_commit() {
    asm volatile("cp.async.commit_group;" ::: "memory");
}
template <int N>
__device__ __forceinline__ void cp_wait() {
    asm volatile("cp.async.wait_group %0;" :: "n"(N) : "memory");
}

// ---------------------------------------------------------------------------
// Unified prep kernel (one launch):
//   bids [0,8192):      x -> half (2M float4)
//   bids [8192,11264):  transpose Wqkv [1024,3072] -> [3072,1024] half
//   bids [11264,12288): transpose Wout [1024,1024] -> [1024,1024] half
//   bid 0 also zeroes the pipeline flags.
// ---------------------------------------------------------------------------
#define PREP_GRID 12288

__global__ __launch_bounds__(256) void prep_kernel(
    const float* __restrict__ x,
    const float* __restrict__ Wqkv,
    const float* __restrict__ Wout)
{
    __shared__ float t[32][33];
    const int bid = blockIdx.x;
    const int tid = threadIdx.x;

    if (bid == 0 && tid < 64) {
        g_cnt0[tid] = 0;
        g_cnt1[tid] = 0;
    }

    if (bid < 8192) {
        int i = bid * 256 + tid;
        float4 v = ((const float4*)x)[i];
        __half2* o = (__half2*)(g_x16 + (size_t)i * 4);
        o[0] = __floats2half2_rn(v.x, v.y);
        o[1] = __floats2half2_rn(v.z, v.w);
        return;
    }

    // transpose: in [R=1024, Ccols], out [Ccols, 1024] half
    const float* in;
    __half* outp;
    int Ccols, bx, by;
    if (bid < 11264) {
        int id = bid - 8192;           // 96 x 32 tiles
        in = Wqkv; outp = g_wqkvT16; Ccols = 3072;
        bx = (id % 96) * 32; by = (id / 96) * 32;
    } else {
        int id = bid - 11264;          // 32 x 32 tiles
        in = Wout; outp = g_woutT16; Ccols = 1024;
        bx = (id % 32) * 32; by = (id / 32) * 32;
    }
    const int xL = tid & 31;
    const int yL = tid >> 5;           // 0..7
#pragma unroll
    for (int j = 0; j < 32; j += 8)
        t[yL + j][xL] = in[(size_t)(by + yL + j) * Ccols + bx + xL];
    __syncthreads();
#pragma unroll
    for (int j = 0; j < 32; j += 8)
        outp[(size_t)(bx + yL + j) * 1024 + by + xL] = __float2half_rn(t[xL][yL + j]);
}

// ---------------------------------------------------------------------------
// FP16 GEMM body: C[m0..][N] tile = A @ Bt^T + bias (fp32 acc)
// BM=128 BN=128 BK=64 halves, 256 threads (8 warps 2x4), warp tile 64x32.
// cp.async 3-stage, 1 sync/iter, ldmatrix both operands.
// MODE 0: convert to half + scatter q (scaled by QSCALE) / k (BHTD, half2)
//         and vt (BHDT, scalar).
// MODE 1: fp32 row-major store (float2) + bias.
// ---------------------------------------------------------------------------
#define GKT 16                    // k-tiles (K=1024 / 64)
#define STAGE_B 16384             // 128 rows x 128B
#define GEMM_SMEM (6 * STAGE_B)   // 3 stages x (A+B) = 98304

template <int MODE>
__device__ __forceinline__ void gemm_body(
    char* smem, const __half* __restrict__ Ag, const __half* __restrict__ Bg,
    const float* __restrict__ bias, float* __restrict__ Cout, int N,
    int m0, int n0)
{
    const uint32_t sA = smem_u32(smem);
    const uint32_t sB = sA + 3 * STAGE_B;

    const int tid  = threadIdx.x;
    const int lane = tid & 31;
    const int wid  = tid >> 5;
    const int wr   = (wid >> 2) * 64;
    const int wc   = (wid & 3) * 32;

    const int lr = tid >> 3;      // + i*32
    const int lg = tid & 7;       // 16B group (8 halves)

    auto issue = [&](int kt) {
        const int s = kt % 3;
#pragma unroll
        for (int i = 0; i < 4; i++) {
            int r = lr + i * 32;
            uint32_t off = r * 128 + ((lg ^ (r & 7)) << 4);
            cp_async16(sA + s * STAGE_B + off,
                       Ag + (size_t)(m0 + r) * 1024 + kt * 64 + lg * 8);
            cp_async16(sB + s * STAGE_B + off,
                       Bg + (size_t)(n0 + r) * 1024 + kt * 64 + lg * 8);
        }
        cp_commit();
    };

    const int arow  = wr + (lane & 7) + 8 * ((lane >> 3) & 1);
    const int kha   = lane >> 4;
    const int brow0 = wc + (lane & 7) + 8 * (lane >> 4);
    const int khb   = (lane >> 3) & 1;

    float acc[4][4][4];
#pragma unroll
    for (int mi = 0; mi < 4; mi++)
#pragma unroll
        for (int ni = 0; ni < 4; ni++)
#pragma unroll
            for (int r = 0; r < 4; r++) acc[mi][ni][r] = 0.0f;

    issue(0);
    issue(1);

    for (int kt = 0; kt < GKT; kt++) {
        if (kt + 1 < GKT) cp_wait<1>(); else cp_wait<0>();
        __syncthreads();
        if (kt + 2 < GKT) issue(kt + 2);

        const int s = kt % 3;
        const uint32_t aS = sA + s * STAGE_B;
        const uint32_t bS = sB + s * STAGE_B;

#pragma unroll
        for (int kk = 0; kk < 4; kk++) {
            uint32_t af[4][4];
#pragma unroll
            for (int mi = 0; mi < 4; mi++) {
                int r = arow + mi * 16;
                uint32_t addr = aS + r * 128 +
                                ((((kk << 1) | kha) ^ (r & 7)) << 4);
                ldsm_x4(af[mi], addr);
            }
            uint32_t bf[4][2];
#pragma unroll
            for (int p = 0; p < 2; p++) {
                int r = brow0 + p * 16;
                uint32_t addr = bS + r * 128 +
                                ((((kk << 1) | khb) ^ (r & 7)) << 4);
                uint32_t d[4];
                ldsm_x4(d, addr);
                bf[2 * p][0] = d[0]; bf[2 * p][1] = d[1];
                bf[2 * p + 1][0] = d[2]; bf[2 * p + 1][1] = d[3];
            }
#pragma unroll
            for (int mi = 0; mi < 4; mi++)
#pragma unroll
                for (int ni = 0; ni < 4; ni++)
                    mma_f16(acc[mi][ni], af[mi], bf[ni], acc[mi][ni]);
        }
    }

    // Epilogue (vectorized: col, col+1 are adjacent; col is even)
    const int g  = lane >> 2;
    const int tg = lane & 3;
#pragma unroll
    for (int mi = 0; mi < 4; mi++) {
        const int row0 = m0 + wr + mi * 16 + g;
        const int row1 = row0 + 8;
#pragma unroll
        for (int ni = 0; ni < 4; ni++) {
            const int col = n0 + wc + ni * 8 + tg * 2;
            const float b0 = __ldg(&bias[col]);
            const float b1 = __ldg(&bias[col + 1]);
            float v00 = acc[mi][ni][0] + b0;   // row0, col
            float v01 = acc[mi][ni][1] + b1;   // row0, col+1
            float v10 = acc[mi][ni][2] + b0;   // row1, col
            float v11 = acc[mi][ni][3] + b1;   // row1, col+1
            if (MODE == 0) {
                const int which = col >> 10;            // same for col+1
                const int rr = col & (C_ - 1);
                const int h = rr >> 6;
                const int d0 = rr & 63;
                const int b0i = row0 >> 11;
                const int t0 = row0 & (T_ - 1);
                const int t1 = row1 & (T_ - 1);
                const size_t bhh = (size_t)(b0i * H_ + h);
                if (which == 2) {
                    // vt[B,H,D,T]: adjacent cols -> different rows, scalar
                    __half* vt = g_vt16 + (bhh * D_ + d0) * T_;
                    vt[t0]      = __float2half_rn(v00);
                    vt[T_ + t0] = __float2half_rn(v01);
                    vt[t1]      = __float2half_rn(v10);
                    vt[T_ + t1] = __float2half_rn(v11);
                } else {
                    if (which == 0) {
                        v00 *= QSCALE; v01 *= QSCALE;
                        v10 *= QSCALE; v11 *= QSCALE;
                    }
                    __half* dst = (which == 0) ? g_q16 : g_k16;
                    __half* p0 = dst + (bhh * T_ + t0) * D_ + d0;
                    __half* p1 = dst + (bhh * T_ + t1) * D_ + d0;
                    *(__half2*)p0 = __floats2half2_rn(v00, v01);
                    *(__half2*)p1 = __floats2half2_rn(v10, v11);
                }
            } else {
                *(float2*)&Cout[(size_t)row0 * N + col] = make_float2(v00, v01);
                *(float2*)&Cout[(size_t)row1 * N + col] = make_float2(v10, v11);
            }
        }
    }
}

// ---------------------------------------------------------------------------
// Flash attention body (causal), fp16 mma, BQ=128 BKV=64, 256 threads
// (8 warps, one 16-row q slab each). FA2: P in registers (computed in packed
// fp16 via ex2.approx.f16x2). l via ones-column MMA. Q + K/Vt all cp.async
// (Q joins the j=0 commit group). 3-stage K/Vt ring, 1 sync/iter.
// Fully-masked warps skip compute on the last diagonal tile.
// ---------------------------------------------------------------------------
#define AQB 16384                        // Q: 128 rows x 128B
#define AKV 8192                         // K/Vt tile: 64 rows x 128B
#define AQ_OFF 0
#define AK_OFF AQB                       // + s*AKV   (3 stages)
#define AV_OFF (AQB + 3 * AKV)           // + s*AKV   (3 stages)

__device__ __forceinline__ void attn_body(char* smc, int b, int h, int qi)
{
    const uint32_t sQ = smem_u32(smc);
    const int bh  = b * H_ + h;
    const int tid = threadIdx.x;
    const int lane = tid & 31;
    const int wid  = tid >> 5;
    const int g    = lane >> 2;
    const int tg   = lane & 3;

    const __half* Qg  = g_q16  + ((size_t)bh * T_ + qi * 128) * D_;
    const __half* Kg  = g_k16  + (size_t)bh * T_ * D_;
    const __half* Vtg = g_vt16 + (size_t)bh * D_ * T_;

    auto issue = [&](int j) {
        const int s = j % 3;
#pragma unroll
        for (int it = 0; it < 2; it++) {
            int i = tid + it * 256;
            int r = i >> 3, gg = i & 7;
            uint32_t sw = r * 128 + ((gg ^ (r & 7)) << 4);
            cp_async16(sQ + AK_OFF + s * AKV + sw,
                       Kg + ((size_t)j * 64 + r) * 64 + gg * 8);
            cp_async16(sQ + AV_OFF + s * AKV + sw,
                       Vtg + (size_t)r * T_ + j * 64 + gg * 8);
        }
        cp_commit();
    };

    // Q tile (128x64 halves) -> swizzled smem via cp.async;
    // joins the j=0 commit group below (issue(0) ends with cp_commit).
#pragma unroll
    for (int it = 0; it < 4; it++) {
        int i = tid + it * 256;
        int r = i >> 3, gg = i & 7;
        uint32_t sw = r * 128 + ((gg ^ (r & 7)) << 4);
        cp_async16(sQ + AQ_OFF + sw, Qg + (size_t)r * 64 + gg * 8);
    }

    const int jmax = 2 * qi + 1;
    issue(0);       // commits {Q, K0, V0}
    issue(1);

    // fragment lane constants
    const int qrow = wid * 16 + (lane & 7) + 8 * ((lane >> 3) & 1);
    const int khq  = lane >> 4;
    const int qxk  = qrow & 7;
    const uint32_t qbase = sQ + AQ_OFF + qrow * 128;
    const int brow = (lane & 7) + 8 * (lane >> 4);    // + p*16
    const int khb  = (lane >> 3) & 1;

    // ones b-fragment for row-sum MMA (1.0h packed twice)
    const uint32_t bf_ones[2] = {0x3C003C00u, 0x3C003C00u};

    float O[8][4];
#pragma unroll
    for (int ni = 0; ni < 8; ni++)
#pragma unroll
        for (int r = 0; r < 4; r++) O[ni][r] = 0.0f;
    float lacc[4] = {0.0f, 0.0f, 0.0f, 0.0f};   // l in cols (duplicated)
    float mrow0 = -1e30f, mrow1 = -1e30f;

    const int rloc = wid * 16 + g;
    const int wtop = qi * 128 + wid * 16 + 15;   // warp's highest global row

    for (int j = 0; j <= jmax; j++) {
        const int s = j % 3;
        if (j < jmax) cp_wait<1>(); else cp_wait<0>();
        __syncthreads();
        if (j + 2 <= jmax) issue(j + 2);

        // Fully-masked warp on this tile? (all rows < first kv col)
        if (wtop < j * 64) continue;

        const uint32_t kS = sQ + AK_OFF + s * AKV;
        const uint32_t vS = sQ + AV_OFF + s * AKV;

        // S = Q K^T  (fp32 accum; scale pre-folded into q)
        float sfr[8][4];
#pragma unroll
        for (int ni = 0; ni < 8; ni++)
#pragma unroll
            for (int r = 0; r < 4; r++) sfr[ni][r] = 0.0f;

#pragma unroll
        for (int kk = 0; kk < 4; kk++) {
            uint32_t af[4];
            ldsm_x4(af, qbase + ((((kk << 1) | khq) ^ qxk) << 4));
            uint32_t bf[8][2];
#pragma unroll
            for (int p = 0; p < 4; p++) {
                int r = brow + p * 16;
                uint32_t d[4];
                ldsm_x4(d, kS + r * 128 + ((((kk << 1) | khb) ^ (r & 7)) << 4));
                bf[2 * p][0] = d[0]; bf[2 * p][1] = d[1];
                bf[2 * p + 1][0] = d[2]; bf[2 * p + 1][1] = d[3];
            }
#pragma unroll
            for (int ni = 0; ni < 8; ni++)
                mma_f16(sfr[ni], af, bf[ni], sfr[ni]);
        }

        // Causal mask (last two kv tiles straddle diagonal)
        const bool diag = (j >= 2 * qi);
        const int rowg0 = qi * 128 + rloc;
        const int rowg1 = rowg0 + 8;
        if (diag) {
#pragma unroll
            for (int ni = 0; ni < 8; ni++) {
#pragma unroll
                for (int r = 0; r < 4; r++) {
                    int colg = j * 64 + ni * 8 + tg * 2 + (r & 1);
                    int rowg = (r >> 1) ? rowg1 : rowg0;
                    if (colg > rowg) sfr[ni][r] = -1e30f;
                }
            }
        }

        // Online softmax max (two rows per thread)
        float mx0 = -1e30f, mx1 = -1e30f;
#pragma unroll
        for (int ni = 0; ni < 8; ni++) {
            mx0 = fmaxf(mx0, fmaxf(sfr[ni][0], sfr[ni][1]));
            mx1 = fmaxf(mx1, fmaxf(sfr[ni][2], sfr[ni][3]));
        }
        mx0 = fmaxf(mx0, __shfl_xor_sync(0xffffffffu, mx0, 1));
        mx0 = fmaxf(mx0, __shfl_xor_sync(0xffffffffu, mx0, 2));
        mx1 = fmaxf(mx1, __shfl_xor_sync(0xffffffffu, mx1, 1));
        mx1 = fmaxf(mx1, __shfl_xor_sync(0xffffffffu, mx1, 2));

        float mn0 = fmaxf(mrow0, mx0);
        float mn1 = fmaxf(mrow1, mx1);
        float a0 = ex2f(mrow0 - mn0);
        float a1 = ex2f(mrow1 - mn1);
        mrow0 = mn0;
        mrow1 = mn1;

        // P = 2^(s - m) computed directly in packed fp16 (ex2.approx.f16x2):
        // P0[ni] = rows g (cols ni*8+2tg, +1), P1[ni] = rows g+8.
        uint32_t P0[8], P1[8];
#pragma unroll
        for (int ni = 0; ni < 8; ni++) {
            P0[ni] = h2ex2(packh2(sfr[ni][0] - mn0, sfr[ni][1] - mn0));
            P1[ni] = h2ex2(packh2(sfr[ni][2] - mn1, sfr[ni][3] - mn1));
        }

        // Rescale O and l
#pragma unroll
        for (int ni = 0; ni < 8; ni++) {
            O[ni][0] *= a0; O[ni][1] *= a0;
            O[ni][2] *= a1; O[ni][3] *= a1;
        }
        lacc[0] *= a0; lacc[1] *= a0;
        lacc[2] *= a1; lacc[3] *= a1;

        // O += P @ V ; l += P @ 1 (FA2 repack: P fragments already packed)
#pragma unroll
        for (int kk = 0; kk < 4; kk++) {
            uint32_t af[4];
            af[0] = P0[2 * kk];
            af[1] = P1[2 * kk];
            af[2] = P0[2 * kk + 1];
            af[3] = P1[2 * kk + 1];
            uint32_t bf[8][2];
#pragma unroll
            for (int p = 0; p < 4; p++) {
                int r = brow + p * 16;
                uint32_t d[4];
                ldsm_x4(d, vS + r * 128 + ((((kk << 1) | khb) ^ (r & 7)) << 4));
                bf[2 * p][0] = d[0]; bf[2 * p][1] = d[1];
                bf[2 * p + 1][0] = d[2]; bf[2 * p + 1][1] = d[3];
            }
#pragma unroll
            for (int ni = 0; ni < 8; ni++)
                mma_f16(O[ni], af, bf[ni], O[ni]);
            mma_f16(lacc, af, bf_ones, lacc);
        }
    }

    // Epilogue: O /= l (l cols are duplicated; [0]=row g, [2]=row g+8)
    float il0 = 1.0f / lacc[0];
    float il1 = 1.0f / lacc[2];
    int t0 = qi * 128 + rloc;
#pragma unroll
    for (int ni = 0; ni < 8; ni++) {
        int d = ni * 8 + tg * 2;
        size_t base0 = ((size_t)(b * T_ + t0    ) * H_ + h) * D_ + d;
        size_t base1 = ((size_t)(b * T_ + t0 + 8) * H_ + h) * D_ + d;
        *(__half2*)&g_y16[base0] = __floats2half2_rn(O[ni][0] * il0, O[ni][1] * il0);
        *(__half2*)&g_y16[base1] = __floats2half2_rn(O[ni][2] * il1, O[ni][3] * il1);
    }
}

// ---------------------------------------------------------------------------
// Mega kernel: grid-level pipeline, PHASE-BLOCKED ordering (R11 schedule).
//   bids [0,1536):    qkv gemm tiles, row-groups ascending -> cnt0[rt]++
//   bids [1536,2560): attention (qi ascending), gated on cnt0 -> cnt1[grp]++
//   bids [2560,3072): out-proj tiles, gated on cnt1[grp]==16
// Consumers only wait on strictly-lower-bid producers.
// ---------------------------------------------------------------------------
#define MEGA_GRID 3072

__global__ __launch_bounds__(256, 2) void mega_kernel(
    const float* __restrict__ bqkv, const float* __restrict__ bout,
    float* __restrict__ out)
{
    extern __shared__ char smc[];
    const int bid = blockIdx.x;

    if (bid < 1536) {
        // ---- QKV GEMM tile ----
        int rt_pos = bid / 24;               // 0..63, ascending t-group
        int ct = bid - rt_pos * 24;          // 0..23
        int qi_r = rt_pos >> 2;              // t-tile within batch
        int b = rt_pos & 3;
        int rt = b * 16 + qi_r;              // row-tile id (= cnt0 index)
        gemm_body<0>(smc, g_x16, g_wqkvT16, bqkv, nullptr, 3 * C_,
                     rt * 128, ct * 128);
        __syncthreads();
        if (threadIdx.x == 0) {
            __threadfence();
            atomicAdd(&g_cnt0[rt], 1);
        }
    } else if (bid < 2560) {
        // ---- attention ----
        int idx = bid - 1536;
        int qi = idx >> 6;                   // ascending qi
        int bh = idx & 63;
        int b = bh >> 4;
        int h = bh & 15;
        if (threadIdx.x == 0) {
            for (int i = 0; i <= qi; i++)
                while (atomicAdd(&g_cnt0[b * 16 + i], 0) < 24) __nanosleep(128);
        }
        __syncthreads();
        attn_body(smc, b, h, qi);
        __syncthreads();
        if (threadIdx.x == 0) {
            __threadfence();
            atomicAdd(&g_cnt1[b * 16 + qi], 1);
        }
    } else {
        // ---- out-projection tile ----
        int idx = bid - 2560;
        int qi_g = idx >> 5;                 // ascending qi
        int b = (idx >> 3) & 3;
        int c = idx & 7;
        int grp = b * 16 + qi_g;
        if (threadIdx.x == 0) {
            while (atomicAdd(&g_cnt1[grp], 0) < 16) __nanosleep(128);
        }
        __syncthreads();
        gemm_body<1>(smc, g_y16, g_woutT16, bout, out, C_,
                     grp * 128, c * 128);
    }
}

// ---------------------------------------------------------------------------
// Launch
// ---------------------------------------------------------------------------
extern "C" void kernel_launch(void* const* d_in, const int* in_sizes, int n_in,
                              void* d_out, int out_size)
{
    const float* x     = (const float*)d_in[0];
    const float* Wqkv  = (const float*)d_in[1];
    const float* bqkv  = (const float*)d_in[2];
    const float* Wout  = (const float*)d_in[3];
    const float* bout  = (const float*)d_in[4];
    float* out = (float*)d_out;

    cudaFuncSetAttribute(mega_kernel,
                         cudaFuncAttributeMaxDynamicSharedMemorySize, GEMM_SMEM);

    // 0) prep: x -> half, W^T -> half, zero flags (one launch)
    prep_kernel<<<PREP_GRID, 256>>>(x, Wqkv, Wout);

    // 1) fused qkv-gemm -> attention -> out-proj pipeline, one launch
    mega_kernel<<<MEGA_GRID, 256, GEMM_SMEM>>>(bqkv, bout, out);
}

// round 16
// speedup vs baseline: 1.3571x; 1.0038x over previous
#include <cuda_runtime.h>
#include <cuda_fp16.h>
#include <cstdint>
#include <math.h>

// Problem constants
#define B_ 4
#define T_ 2048
#define C_ 1024
#define H_ 16
#define D_ 64
#define BH_ (B_ * H_)

// softmax scale folded into q: 1/sqrt(D) * log2(e)
#define QSCALE 0.18033688011112042f

// Scratch (device globals -- no allocation allowed)
__device__ __half g_q16[BH_ * T_ * D_];     // [B,H,T,D], pre-scaled by QSCALE
__device__ __half g_k16[BH_ * T_ * D_];     // [B,H,T,D]
__device__ __half g_vt16[BH_ * D_ * T_];    // [B,H,D,T]  (V transposed)
__device__ __half g_y16[B_ * T_ * C_];      // [B,T,C]
__device__ __half g_x16[B_ * T_ * C_];      // x -> half
__device__ __half g_wqkvT16[3 * C_ * C_];   // [3C, C] = W_qkv^T
__device__ __half g_woutT16[C_ * C_];       // [C, C]  = W_out^T

// Flag counters for the in-kernel pipeline (zeroed by prep each call)
__device__ int g_cnt0[64];   // per qkv row-tile: col-tiles done (24 = ready)
__device__ int g_cnt1[64];   // per (b,qi) group: heads done (16 = ready)

// ---------------------------------------------------------------------------
// Helpers
// ---------------------------------------------------------------------------
__device__ __forceinline__ uint32_t smem_u32(const void* p) {
    return (uint32_t)__cvta_generic_to_shared(p);
}

__device__ __forceinline__ float ex2f(float x) {
    float y;
    asm("ex2.approx.f32 %0, %1;" : "=f"(y) : "f"(x));
    return y;
}

__device__ __forceinline__ uint32_t packh2(float a, float b) {
    __half2 h = __floats2half2_rn(a, b);
    return *(uint32_t*)&h;
}

// packed fp16x2 2^x (P is fp16-rounded immediately after anyway)
__device__ __forceinline__ uint32_t h2ex2(uint32_t x) {
    uint32_t y;
    asm("ex2.approx.f16x2 %0, %1;" : "=r"(y) : "r"(x));
    return y;
}

__device__ __forceinline__ void mma_f16(float d[4], const uint32_t a[4],
                                        const uint32_t b[2], const float c[4]) {
    asm volatile(
        "mma.sync.aligned.m16n8k16.row.col.f32.f16.f16.f32 "
        "{%0,%1,%2,%3},{%4,%5,%6,%7},{%8,%9},{%10,%11,%12,%13};"
        : "=f"(d[0]), "=f"(d[1]), "=f"(d[2]), "=f"(d[3])
        : "r"(a[0]), "r"(a[1]), "r"(a[2]), "r"(a[3]),
          "r"(b[0]), "r"(b[1]),
          "f"(c[0]), "f"(c[1]), "f"(c[2]), "f"(c[3]));
}

__device__ __forceinline__ void ldsm_x4(uint32_t d[4], uint32_t saddr) {
    asm volatile(
        "ldmatrix.sync.aligned.m8n8.x4.shared.b16 {%0,%1,%2,%3}, [%4];"
        : "=r"(d[0]), "=r"(d[1]), "=r"(d[2]), "=r"(d[3]) : "r"(saddr));
}

__device__ __forceinline__ void cp_async16(uint32_t dst, const void* src) {
    asm volatile("cp.async.cg.shared.global [%0], [%1], 16;"
                 :: "r"(dst), "l"(src) : "memory");
}
__device__ __forceinline__ void cp_commit() {
    asm volatile("cp.async.commit_group;" ::: "memory");
}
template <int N>
__device__ __forceinline__ void cp_wait() {
    asm volatile("cp.async.wait_group %0;" :: "n"(N) : "memory");
}

// ---------------------------------------------------------------------------
// Unified prep kernel (one launch):
//   bids [0,8192):      x -> half (2M float4)
//   bids [8192,11264):  transpose Wqkv [1024,3072] -> [3072,1024] half
//   bids [11264,12288): transpose Wout [1024,1024] -> [1024,1024] half
//   bid 0 also zeroes the pipeline flags.
// ---------------------------------------------------------------------------
#define PREP_GRID 12288

__global__ __launch_bounds__(256) void prep_kernel(
    const float* __restrict__ x,
    const float* __restrict__ Wqkv,
    const float* __restrict__ Wout)
{
    __shared__ float t[32][33];
    const int bid = blockIdx.x;
    const int tid = threadIdx.x;

    if (bid == 0 && tid < 64) {
        g_cnt0[tid] = 0;
        g_cnt1[tid] = 0;
    }

    if (bid < 8192) {
        int i = bid * 256 + tid;
        float4 v = ((const float4*)x)[i];
        __half2* o = (__half2*)(g_x16 + (size_t)i * 4);
        o[0] = __floats2half2_rn(v.x, v.y);
        o[1] = __floats2half2_rn(v.z, v.w);
        return;
    }

    // transpose: in [R=1024, Ccols], out [Ccols, 1024] half
    const float* in;
    __half* outp;
    int Ccols, bx, by;
    if (bid < 11264) {
        int id = bid - 8192;           // 96 x 32 tiles
        in = Wqkv; outp = g_wqkvT16; Ccols = 3072;
        bx = (id % 96) * 32; by = (id / 96) * 32;
    } else {
        int id = bid - 11264;          // 32 x 32 tiles
        in = Wout; outp = g_woutT16; Ccols = 1024;
        bx = (id % 32) * 32; by = (id / 32) * 32;
    }
    const int xL = tid & 31;
    const int yL = tid >> 5;           // 0..7
#pragma unroll
    for (int j = 0; j < 32; j += 8)
        t[yL + j][xL] = in[(size_t)(by + yL + j) * Ccols + bx + xL];
    __syncthreads();
#pragma unroll
    for (int j = 0; j < 32; j += 8)
        outp[(size_t)(bx + yL + j) * 1024 + by + xL] = __float2half_rn(t[xL][yL + j]);
}

// ---------------------------------------------------------------------------
// FP16 GEMM body: C[m0..][N] tile = A @ Bt^T + bias (fp32 acc)
// BM=128 BN=128 BK=64 halves, 256 threads (8 warps 2x4), warp tile 64x32.
// cp.async 3-stage, 1 sync/iter, ldmatrix both operands.
// MODE 0: convert to half + scatter q (scaled by QSCALE) / k (BHTD, half2)
//         and vt (BHDT, scalar).
// MODE 1: fp32 row-major store (float2) + bias.
// ---------------------------------------------------------------------------
#define GKT 16                    // k-tiles (K=1024 / 64)
#define STAGE_B 16384             // 128 rows x 128B
#define GEMM_SMEM (6 * STAGE_B)   // 3 stages x (A+B) = 98304

template <int MODE>
__device__ __forceinline__ void gemm_body(
    char* smem, const __half* __restrict__ Ag, const __half* __restrict__ Bg,
    const float* __restrict__ bias, float* __restrict__ Cout, int N,
    int m0, int n0)
{
    const uint32_t sA = smem_u32(smem);
    const uint32_t sB = sA + 3 * STAGE_B;

    const int tid  = threadIdx.x;
    const int lane = tid & 31;
    const int wid  = tid >> 5;
    const int wr   = (wid >> 2) * 64;
    const int wc   = (wid & 3) * 32;

    const int lr = tid >> 3;      // + i*32
    const int lg = tid & 7;       // 16B group (8 halves)

    auto issue = [&](int kt) {
        const int s = kt % 3;
#pragma unroll
        for (int i = 0; i < 4; i++) {
            int r = lr + i * 32;
            uint32_t off = r * 128 + ((lg ^ (r & 7)) << 4);
            cp_async16(sA + s * STAGE_B + off,
                       Ag + (size_t)(m0 + r) * 1024 + kt * 64 + lg * 8);
            cp_async16(sB + s * STAGE_B + off,
                       Bg + (size_t)(n0 + r) * 1024 + kt * 64 + lg * 8);
        }
        cp_commit();
    };

    const int arow  = wr + (lane & 7) + 8 * ((lane >> 3) & 1);
    const int kha   = lane >> 4;
    const int brow0 = wc + (lane & 7) + 8 * (lane >> 4);
    const int khb   = (lane >> 3) & 1;

    float acc[4][4][4];
#pragma unroll
    for (int mi = 0; mi < 4; mi++)
#pragma unroll
        for (int ni = 0; ni < 4; ni++)
#pragma unroll
            for (int r = 0; r < 4; r++) acc[mi][ni][r] = 0.0f;

    issue(0);
    issue(1);

    for (int kt = 0; kt < GKT; kt++) {
        if (kt + 1 < GKT) cp_wait<1>(); else cp_wait<0>();
        __syncthreads();
        if (kt + 2 < GKT) issue(kt + 2);

        const int s = kt % 3;
        const uint32_t aS = sA + s * STAGE_B;
        const uint32_t bS = sB + s * STAGE_B;

#pragma unroll
        for (int kk = 0; kk < 4; kk++) {
            uint32_t af[4][4];
#pragma unroll
            for (int mi = 0; mi < 4; mi++) {
                int r = arow + mi * 16;
                uint32_t addr = aS + r * 128 +
                                ((((kk << 1) | kha) ^ (r & 7)) << 4);
                ldsm_x4(af[mi], addr);
            }
            uint32_t bf[4][2];
#pragma unroll
            for (int p = 0; p < 2; p++) {
                int r = brow0 + p * 16;
                uint32_t addr = bS + r * 128 +
                                ((((kk << 1) | khb) ^ (r & 7)) << 4);
                uint32_t d[4];
                ldsm_x4(d, addr);
                bf[2 * p][0] = d[0]; bf[2 * p][1] = d[1];
                bf[2 * p + 1][0] = d[2]; bf[2 * p + 1][1] = d[3];
            }
#pragma unroll
            for (int mi = 0; mi < 4; mi++)
#pragma unroll
                for (int ni = 0; ni < 4; ni++)
                    mma_f16(acc[mi][ni], af[mi], bf[ni], acc[mi][ni]);
        }
    }

    // Epilogue (vectorized: col, col+1 are adjacent; col is even)
    const int g  = lane >> 2;
    const int tg = lane & 3;
#pragma unroll
    for (int mi = 0; mi < 4; mi++) {
        const int row0 = m0 + wr + mi * 16 + g;
        const int row1 = row0 + 8;
#pragma unroll
        for (int ni = 0; ni < 4; ni++) {
            const int col = n0 + wc + ni * 8 + tg * 2;
            const float b0 = __ldg(&bias[col]);
            const float b1 = __ldg(&bias[col + 1]);
            float v00 = acc[mi][ni][0] + b0;   // row0, col
            float v01 = acc[mi][ni][1] + b1;   // row0, col+1
            float v10 = acc[mi][ni][2] + b0;   // row1, col
            float v11 = acc[mi][ni][3] + b1;   // row1, col+1
            if (MODE == 0) {
                const int which = col >> 10;            // same for col+1
                const int rr = col & (C_ - 1);
                const int h = rr >> 6;
                const int d0 = rr & 63;
                const int b0i = row0 >> 11;
                const int t0 = row0 & (T_ - 1);
                const int t1 = row1 & (T_ - 1);
                const size_t bhh = (size_t)(b0i * H_ + h);
                if (which == 2) {
                    // vt[B,H,D,T]: adjacent cols -> different rows, scalar
                    __half* vt = g_vt16 + (bhh * D_ + d0) * T_;
                    vt[t0]      = __float2half_rn(v00);
                    vt[T_ + t0] = __float2half_rn(v01);
                    vt[t1]      = __float2half_rn(v10);
                    vt[T_ + t1] = __float2half_rn(v11);
                } else {
                    if (which == 0) {
                        v00 *= QSCALE; v01 *= QSCALE;
                        v10 *= QSCALE; v11 *= QSCALE;
                    }
                    __half* dst = (which == 0) ? g_q16 : g_k16;
                    __half* p0 = dst + (bhh * T_ + t0) * D_ + d0;
                    __half* p1 = dst + (bhh * T_ + t1) * D_ + d0;
                    *(__half2*)p0 = __floats2half2_rn(v00, v01);
                    *(__half2*)p1 = __floats2half2_rn(v10, v11);
                }
            } else {
                *(float2*)&Cout[(size_t)row0 * N + col] = make_float2(v00, v01);
                *(float2*)&Cout[(size_t)row1 * N + col] = make_float2(v10, v11);
            }
        }
    }
}

// ---------------------------------------------------------------------------
// Flash attention body (causal), fp16 mma, BQ=128 BKV=64, 256 threads
// (8 warps, one 16-row q slab each). FA2: P in registers (packed fp16 ex2).
// Q fragments hoisted into registers (loaded once at j=0). l via ones-column
// MMA. Warp-uniform skip of O/l renorm when no new row max (exact: a==1).
// Q + K/Vt all cp.async; 3-stage K/Vt ring, 1 sync/iter. Fully-masked warps
// skip compute on the last diagonal tile.
// ---------------------------------------------------------------------------
#define AQB 16384                        // Q: 128 rows x 128B
#define AKV 8192                         // K/Vt tile: 64 rows x 128B
#define AQ_OFF 0
#define AK_OFF AQB                       // + s*AKV   (3 stages)
#define AV_OFF (AQB + 3 * AKV)           // + s*AKV   (3 stages)

__device__ __forceinline__ void attn_body(char* smc, int b, int h, int qi)
{
    const uint32_t sQ = smem_u32(smc);
    const int bh  = b * H_ + h;
    const int tid = threadIdx.x;
    const int lane = tid & 31;
    const int wid  = tid >> 5;
    const int g    = lane >> 2;
    const int tg   = lane & 3;

    const __half* Qg  = g_q16  + ((size_t)bh * T_ + qi * 128) * D_;
    const __half* Kg  = g_k16  + (size_t)bh * T_ * D_;
    const __half* Vtg = g_vt16 + (size_t)bh * D_ * T_;

    auto issue = [&](int j) {
        const int s = j % 3;
#pragma unroll
        for (int it = 0; it < 2; it++) {
            int i = tid + it * 256;
            int r = i >> 3, gg = i & 7;
            uint32_t sw = r * 128 + ((gg ^ (r & 7)) << 4);
            cp_async16(sQ + AK_OFF + s * AKV + sw,
                       Kg + ((size_t)j * 64 + r) * 64 + gg * 8);
            cp_async16(sQ + AV_OFF + s * AKV + sw,
                       Vtg + (size_t)r * T_ + j * 64 + gg * 8);
        }
        cp_commit();
    };

    // Q tile (128x64 halves) -> swizzled smem via cp.async;
    // joins the j=0 commit group below (issue(0) ends with cp_commit).
#pragma unroll
    for (int it = 0; it < 4; it++) {
        int i = tid + it * 256;
        int r = i >> 3, gg = i & 7;
        uint32_t sw = r * 128 + ((gg ^ (r & 7)) << 4);
        cp_async16(sQ + AQ_OFF + sw, Qg + (size_t)r * 64 + gg * 8);
    }

    const int jmax = 2 * qi + 1;
    issue(0);       // commits {Q, K0, V0}
    issue(1);

    // fragment lane constants
    const int qrow = wid * 16 + (lane & 7) + 8 * ((lane >> 3) & 1);
    const int khq  = lane >> 4;
    const int qxk  = qrow & 7;
    const uint32_t qbase = sQ + AQ_OFF + qrow * 128;
    const int brow = (lane & 7) + 8 * (lane >> 4);    // + p*16
    const int khb  = (lane >> 3) & 1;

    // ones b-fragment for row-sum MMA (1.0h packed twice)
    const uint32_t bf_ones[2] = {0x3C003C00u, 0x3C003C00u};

    uint32_t qf[4][4];      // hoisted Q fragments (loop-invariant)

    float O[8][4];
#pragma unroll
    for (int ni = 0; ni < 8; ni++)
#pragma unroll
        for (int r = 0; r < 4; r++) O[ni][r] = 0.0f;
    float lacc[4] = {0.0f, 0.0f, 0.0f, 0.0f};   // l in cols (duplicated)
    float mrow0 = -1e30f, mrow1 = -1e30f;

    const int rloc = wid * 16 + g;
    const int wtop = qi * 128 + wid * 16 + 15;   // warp's highest global row

    for (int j = 0; j <= jmax; j++) {
        const int s = j % 3;
        if (j < jmax) cp_wait<1>(); else cp_wait<0>();
        __syncthreads();
        if (j + 2 <= jmax) issue(j + 2);

        // Load Q fragments once (Q landed with the j=0 group; j=0 is never
        // skipped since wtop >= 0).
        if (j == 0) {
#pragma unroll
            for (int kk = 0; kk < 4; kk++)
                ldsm_x4(qf[kk], qbase + ((((kk << 1) | khq) ^ qxk) << 4));
        }

        // Fully-masked warp on this tile? (all rows < first kv col)
        if (wtop < j * 64) continue;

        const uint32_t kS = sQ + AK_OFF + s * AKV;
        const uint32_t vS = sQ + AV_OFF + s * AKV;

        // S = Q K^T  (fp32 accum; scale pre-folded into q)
        float sfr[8][4];
#pragma unroll
        for (int ni = 0; ni < 8; ni++)
#pragma unroll
            for (int r = 0; r < 4; r++) sfr[ni][r] = 0.0f;

#pragma unroll
        for (int kk = 0; kk < 4; kk++) {
            uint32_t bf[8][2];
#pragma unroll
            for (int p = 0; p < 4; p++) {
                int r = brow + p * 16;
                uint32_t d[4];
                ldsm_x4(d, kS + r * 128 + ((((kk << 1) | khb) ^ (r & 7)) << 4));
                bf[2 * p][0] = d[0]; bf[2 * p][1] = d[1];
                bf[2 * p + 1][0] = d[2]; bf[2 * p + 1][1] = d[3];
            }
#pragma unroll
            for (int ni = 0; ni < 8; ni++)
                mma_f16(sfr[ni], qf[kk], bf[ni], sfr[ni]);
        }

        // Causal mask (last two kv tiles straddle diagonal)
        const bool diag = (j >= 2 * qi);
        const int rowg0 = qi * 128 + rloc;
        const int rowg1 = rowg0 + 8;
        if (diag) {
#pragma unroll
            for (int ni = 0; ni < 8; ni++) {
#pragma unroll
                for (int r = 0; r < 4; r++) {
                    int colg = j * 64 + ni * 8 + tg * 2 + (r & 1);
                    int rowg = (r >> 1) ? rowg1 : rowg0;
                    if (colg > rowg) sfr[ni][r] = -1e30f;
                }
            }
        }

        // Online softmax max (two rows per thread)
        float mx0 = -1e30f, mx1 = -1e30f;
#pragma unroll
        for (int ni = 0; ni < 8; ni++) {
            mx0 = fmaxf(mx0, fmaxf(sfr[ni][0], sfr[ni][1]));
            mx1 = fmaxf(mx1, fmaxf(sfr[ni][2], sfr[ni][3]));
        }
        mx0 = fmaxf(mx0, __shfl_xor_sync(0xffffffffu, mx0, 1));
        mx0 = fmaxf(mx0, __shfl_xor_sync(0xffffffffu, mx0, 2));
        mx1 = fmaxf(mx1, __shfl_xor_sync(0xffffffffu, mx1, 1));
        mx1 = fmaxf(mx1, __shfl_xor_sync(0xffffffffu, mx1, 2));

        float mn0 = fmaxf(mrow0, mx0);
        float mn1 = fmaxf(mrow1, mx1);
        float a0 = ex2f(mrow0 - mn0);
        float a1 = ex2f(mrow1 - mn1);
        mrow0 = mn0;
        mrow1 = mn1;

        // P = 2^(s - m) computed directly in packed fp16 (ex2.approx.f16x2)
        uint32_t P0[8], P1[8];
#pragma unroll
        for (int ni = 0; ni < 8; ni++) {
            P0[ni] = h2ex2(packh2(sfr[ni][0] - mn0, sfr[ni][1] - mn0));
            P1[ni] = h2ex2(packh2(sfr[ni][2] - mn1, sfr[ni][3] - mn1));
        }

        // Rescale O and l only if some row in the warp got a new max
        // (exact skip: a == 1.0 means multiply-by-identity).
        if (!__all_sync(0xffffffffu, (a0 == 1.0f) && (a1 == 1.0f))) {
#pragma unroll
            for (int ni = 0; ni < 8; ni++) {
                O[ni][0] *= a0; O[ni][1] *= a0;
                O[ni][2] *= a1; O[ni][3] *= a1;
            }
            lacc[0] *= a0; lacc[1] *= a0;
            lacc[2] *= a1; lacc[3] *= a1;
        }

        // O += P @ V ; l += P @ 1 (FA2 repack: P fragments already packed)
#pragma unroll
        for (int kk = 0; kk < 4; kk++) {
            uint32_t af[4];
            af[0] = P0[2 * kk];
            af[1] = P1[2 * kk];
            af[2] = P0[2 * kk + 1];
            af[3] = P1[2 * kk + 1];
            uint32_t bf[8][2];
#pragma unroll
            for (int p = 0; p < 4; p++) {
                int r = brow + p * 16;
                uint32_t d[4];
                ldsm_x4(d, vS + r * 128 + ((((kk << 1) | khb) ^ (r & 7)) << 4));
                bf[2 * p][0] = d[0]; bf[2 * p][1] = d[1];
                bf[2 * p + 1][0] = d[2]; bf[2 * p + 1][1] = d[3];
            }
#pragma unroll
            for (int ni = 0; ni < 8; ni++)
                mma_f16(O[ni], af, bf[ni], O[ni]);
            mma_f16(lacc, af, bf_ones, lacc);
        }
    }

    // Epilogue: O /= l (l cols are duplicated; [0]=row g, [2]=row g+8)
    float il0 = 1.0f / lacc[0];
    float il1 = 1.0f / lacc[2];
    int t0 = qi * 128 + rloc;
#pragma unroll
    for (int ni = 0; ni < 8; ni++) {
        int d = ni * 8 + tg * 2;
        size_t base0 = ((size_t)(b * T_ + t0    ) * H_ + h) * D_ + d;
        size_t base1 = ((size_t)(b * T_ + t0 + 8) * H_ + h) * D_ + d;
        *(__half2*)&g_y16[base0] = __floats2half2_rn(O[ni][0] * il0, O[ni][1] * il0);
        *(__half2*)&g_y16[base1] = __floats2half2_rn(O[ni][2] * il1, O[ni][3] * il1);
    }
}

// ---------------------------------------------------------------------------
// Mega kernel: grid-level pipeline, PHASE-BLOCKED ordering (R11 schedule).
//   bids [0,1536):    qkv gemm tiles, row-groups ascending -> cnt0[rt]++
//   bids [1536,2560): attention (qi ascending), gated on cnt0 -> cnt1[grp]++
//   bids [2560,3072): out-proj tiles, gated on cnt1[grp]==16
// Consumers only wait on strictly-lower-bid producers.
// ---------------------------------------------------------------------------
#define MEGA_GRID 3072

__global__ __launch_bounds__(256, 2) void mega_kernel(
    const float* __restrict__ bqkv, const float* __restrict__ bout,
    float* __restrict__ out)
{
    extern __shared__ char smc[];
    const int bid = blockIdx.x;

    if (bid < 1536) {
        // ---- QKV GEMM tile ----
        int rt_pos = bid / 24;               // 0..63, ascending t-group
        int ct = bid - rt_pos * 24;          // 0..23
        int qi_r = rt_pos >> 2;              // t-tile within batch
        int b = rt_pos & 3;
        int rt = b * 16 + qi_r;              // row-tile id (= cnt0 index)
        gemm_body<0>(smc, g_x16, g_wqkvT16, bqkv, nullptr, 3 * C_,
                     rt * 128, ct * 128);
        __syncthreads();
        if (threadIdx.x == 0) {
            __threadfence();
            atomicAdd(&g_cnt0[rt], 1);
        }
    } else if (bid < 2560) {
        // ---- attention ----
        int idx = bid - 1536;
        int qi = idx >> 6;                   // ascending qi
        int bh = idx & 63;
        int b = bh >> 4;
        int h = bh & 15;
        if (threadIdx.x == 0) {
            for (int i = 0; i <= qi; i++)
                while (atomicAdd(&g_cnt0[b * 16 + i], 0) < 24) __nanosleep(128);
        }
        __syncthreads();
        attn_body(smc, b, h, qi);
        __syncthreads();
        if (threadIdx.x == 0) {
            __threadfence();
            atomicAdd(&g_cnt1[b * 16 + qi], 1);
        }
    } else {
        // ---- out-projection tile ----
        int idx = bid - 2560;
        int qi_g = idx >> 5;                 // ascending qi
        int b = (idx >> 3) & 3;
        int c = idx & 7;
        int grp = b * 16 + qi_g;
        if (threadIdx.x == 0) {
            while (atomicAdd(&g_cnt1[grp], 0) < 16) __nanosleep(128);
        }
        __syncthreads();
        gemm_body<1>(smc, g_y16, g_woutT16, bout, out, C_,
                     grp * 128, c * 128);
    }
}

// ---------------------------------------------------------------------------
// Launch
// ---------------------------------------------------------------------------
extern "C" void kernel_launch(void* const* d_in, const int* in_sizes, int n_in,
                              void* d_out, int out_size)
{
    const float* x     = (const float*)d_in[0];
    const float* Wqkv  = (const float*)d_in[1];
    const float* bqkv  = (const float*)d_in[2];
    const float* Wout  = (const float*)d_in[3];
    const float* bout  = (const float*)d_in[4];
    float* out = (float*)d_out;

    cudaFuncSetAttribute(mega_kernel,
                         cudaFuncAttributeMaxDynamicSharedMemorySize, GEMM_SMEM);

    // 0) prep: x -> half, W^T -> half, zero flags (one launch)
    prep_kernel<<<PREP_GRID, 256>>>(x, Wqkv, Wout);

    // 1) fused qkv-gemm -> attention -> out-proj pipeline, one launch
    mega_kernel<<<MEGA_GRID, 256, GEMM_SMEM>>>(bqkv, bout, out);
}